// round 2
// baseline (speedup 1.0000x reference)
#include <cuda_runtime.h>

#define Tn 24
#define Bn 64
#define Dn 1536
#define Rn 5120
#define Cn 100
#define NSPLIT 8

__device__ float g_WlT[Rn * Rn];             // [r'][r] = Wl[r][r']*lat_mask[r][r']
__device__ float g_xn[Tn * Bn * Dn];
__device__ float g_drive[Tn * Bn * Rn];
__device__ float g_mem[Bn * Rn];
__device__ float g_ttr[Bn * Rn];
__device__ float g_rtr[Bn * Rn];
__device__ float g_ctr[Bn * Rn];
__device__ float g_ssum[Bn * Rn];
__device__ float g_mempre[Bn * Rn];
__device__ float g_partial[NSPLIT][Bn * Rn];
__device__ unsigned long long g_bits[2][Rn]; // bit b of g_bits[cur][r] = spike(b, r)
__device__ int g_act[Rn];
__device__ int g_nact;

// ---------------- init ----------------
__global__ void k_init()
{
    int i = blockIdx.x * 256 + threadIdx.x;
    if (i < Bn * Rn) {
        g_mem[i] = 0.f; g_ttr[i] = 0.f; g_rtr[i] = 0.f; g_ctr[i] = 0.f; g_ssum[i] = 0.f;
    }
    if (i < Rn) { g_bits[0][i] = 0ull; g_bits[1][i] = 0ull; }
    if (i == 0) g_nact = 0;
}

// ---------------- masked transpose of Wl ----------------
__global__ void k_prepW(const float* __restrict__ Wl, const float* __restrict__ lm)
{
    __shared__ float tile[32][33];
    int bx = blockIdx.x * 32;  // r' (col of Wl)
    int by = blockIdx.y * 32;  // r  (row of Wl)
    int x = bx + threadIdx.x;
#pragma unroll
    for (int j = 0; j < 32; j += 8) {
        int y = by + threadIdx.y + j;
        tile[threadIdx.y + j][threadIdx.x] = Wl[y * Rn + x] * lm[y * Rn + x];
    }
    __syncthreads();
    int xo = by + threadIdx.x;  // r
#pragma unroll
    for (int j = 0; j < 32; j += 8) {
        int yo = bx + threadIdx.y + j;  // r'
        g_WlT[yo * Rn + xo] = tile[threadIdx.x][threadIdx.y + j];
    }
}

// ---------------- layernorm ----------------
__global__ void __launch_bounds__(256) k_ln(const float* __restrict__ x,
                                            const float* __restrict__ gw,
                                            const float* __restrict__ gb)
{
    const int row = blockIdx.x;
    const float* xr = x + row * Dn;
    float s = 0.f, s2 = 0.f;
    for (int i = threadIdx.x; i < Dn; i += 256) { float v = xr[i]; s += v; s2 += v * v; }
    __shared__ float sh[64];
    int lane = threadIdx.x & 31, wid = threadIdx.x >> 5;
#pragma unroll
    for (int o = 16; o > 0; o >>= 1) {
        s += __shfl_down_sync(0xffffffffu, s, o);
        s2 += __shfl_down_sync(0xffffffffu, s2, o);
    }
    if (lane == 0) { sh[wid] = s; sh[wid + 32] = s2; }
    __syncthreads();
    if (threadIdx.x == 0) {
        float ts = 0.f, ts2 = 0.f;
        for (int w = 0; w < 8; w++) { ts += sh[w]; ts2 += sh[w + 32]; }
        float mean = ts * (1.0f / Dn);
        float var = ts2 * (1.0f / Dn) - mean * mean;
        sh[0] = mean;
        sh[1] = rsqrtf(var + 1e-5f);
    }
    __syncthreads();
    float mean = sh[0], inv = sh[1];
    for (int i = threadIdx.x; i < Dn; i += 256)
        g_xn[row * Dn + i] = (xr[i] - mean) * inv * gw[i] + gb[i];
}

// ---------------- block-structured drive GEMM ----------------
__global__ void __launch_bounds__(256) k_drive(const float* __restrict__ Wp,
                                               const float* __restrict__ bp)
{
    __shared__ float As[16][128];
    __shared__ float Bs[16][128];
    const int bn = blockIdx.x, bm = blockIdx.y;
    const int nb = (bn * 128) >> 10;  // neuron block 0..4
    const int koff_t[5] = {0, 512, 1024, 1280, 1408};
    const int klen_t[5] = {512, 512, 256, 128, 0};
    const int k0 = koff_t[nb], kl = klen_t[nb];
    const int tid = threadIdx.x;
    const int tx = tid & 15, ty = tid >> 4;
    float acc[8][8];
#pragma unroll
    for (int i = 0; i < 8; i++)
#pragma unroll
        for (int j = 0; j < 8; j++) acc[i][j] = 0.f;

    const int ldm = tid >> 2;
    const int ldk = (tid & 3) << 2;
    for (int kt = 0; kt < kl; kt += 16) {
#pragma unroll
        for (int h = 0; h < 2; h++) {
            int m = ldm + h * 64;
            float4 av = *(const float4*)&g_xn[(bm * 128 + m) * Dn + k0 + kt + ldk];
            As[ldk + 0][m] = av.x; As[ldk + 1][m] = av.y; As[ldk + 2][m] = av.z; As[ldk + 3][m] = av.w;
            float4 bv = *(const float4*)&Wp[(bn * 128 + m) * Dn + k0 + kt + ldk];
            Bs[ldk + 0][m] = bv.x; Bs[ldk + 1][m] = bv.y; Bs[ldk + 2][m] = bv.z; Bs[ldk + 3][m] = bv.w;
        }
        __syncthreads();
#pragma unroll
        for (int k = 0; k < 16; k++) {
            float a[8], b[8];
#pragma unroll
            for (int i = 0; i < 8; i++) a[i] = As[k][ty * 8 + i];
#pragma unroll
            for (int j = 0; j < 8; j++) b[j] = Bs[k][tx * 8 + j];
#pragma unroll
            for (int i = 0; i < 8; i++)
#pragma unroll
                for (int j = 0; j < 8; j++) acc[i][j] += a[i] * b[j];
        }
        __syncthreads();
    }
#pragma unroll
    for (int i = 0; i < 8; i++) {
        int row = bm * 128 + ty * 8 + i;
#pragma unroll
        for (int j = 0; j < 8; j++) {
            int col = bn * 128 + tx * 8 + j;
            g_drive[row * Rn + col] = acc[i][j] + bp[col];
        }
    }
}

// ---------------- lateral recurrence: bitmask conditional adds ----------------
__global__ void __launch_bounds__(256) k_rec(int cur)
{
    const int col = blockIdx.x * 256 + threadIdx.x;
    const int split = blockIdx.y;
    const int total = g_nact;
    const int per = (total + NSPLIT - 1) / NSPLIT;
    int i0 = split * per;
    int i1 = i0 + per; if (i1 > total) i1 = total;
    const unsigned long long* __restrict__ bits = g_bits[cur];
    float acc[64];
#pragma unroll
    for (int b = 0; b < 64; b++) acc[b] = 0.f;
    for (int i = i0; i < i1; i++) {
        int rp = __ldg(&g_act[i]);
        unsigned long long m = __ldg(&bits[rp]);
        float w = __ldg(&g_WlT[rp * Rn + col]);
#pragma unroll
        for (int c8 = 0; c8 < 8; c8++) {
            unsigned ch = (unsigned)(m >> (c8 * 8)) & 0xffu;
            if (ch) {
#pragma unroll
                for (int j = 0; j < 8; j++)
                    if (ch & (1u << j)) acc[c8 * 8 + j] += w;
            }
        }
    }
    float* out = g_partial[split];
#pragma unroll
    for (int b = 0; b < 64; b++) out[b * Rn + col] = acc[b];
}

// ---------------- elementwise pre-WTA membrane ----------------
__global__ void __launch_bounds__(256) k_s1(int cur, int t,
                                            const float* __restrict__ bl,
                                            const float* __restrict__ decp,
                                            const float* __restrict__ refb,
                                            const float* __restrict__ curb)
{
    int idx = blockIdx.x * 256 + threadIdx.x;
    if (idx >= Bn * Rn) return;
    int r = idx % Rn;
    int b = idx / Rn;
    float p = 0.f;
#pragma unroll
    for (int s = 0; s < NSPLIT; s++) p += g_partial[s][idx];
    float mem = g_mem[idx];
    float spk = (float)((g_bits[cur][r] >> b) & 1ull);
    float rtr = g_rtr[idx], ctr = g_ctr[idx];
    float dec = fminf(fmaxf(decp[r], 0.f), 1.f);
    float ref = 0.5f + refb[r] * rtr;
    float cu = curb[r] * ctr;
    float state = g_drive[t * (Bn * Rn) + idx] + p + bl[r];
    g_mempre[idx] = (mem - spk * ref) * dec + state + cu;
}

// ---------------- WTA quantile + spike + traces ----------------
__device__ __forceinline__ unsigned f2key(float f)
{
    unsigned b = __float_as_uint(f);
    return (b & 0x80000000u) ? ~b : (b | 0x80000000u);
}
__device__ __forceinline__ float key2f(unsigned u)
{
    unsigned b = (u & 0x80000000u) ? (u & 0x7fffffffu) : ~u;
    return __uint_as_float(b);
}

__global__ void __launch_bounds__(256) k_s2(int cur,
                                            const float* __restrict__ thb,
                                            const float* __restrict__ thdp,
                                            const float* __restrict__ rfdp,
                                            const float* __restrict__ cudp)
{
    const int b = blockIdx.x, kq = blockIdx.y;
    const int tid = threadIdx.x;
    __shared__ int hist[256];
    __shared__ int wred[8];
    __shared__ int sh_rank;
    __shared__ unsigned sh_prefix;
    __shared__ int sh_cle;
    __shared__ unsigned sh_mg;

    float v[4]; unsigned u[4];
    const int base = b * Rn;
#pragma unroll
    for (int j = 0; j < 4; j++) {
        int r = (tid + j * 256) * 5 + kq;
        v[j] = g_mempre[base + r];
        u[j] = f2key(v[j]);
    }
    if (tid == 0) { sh_prefix = 0u; sh_rank = 818; sh_cle = 0; sh_mg = 0xffffffffu; }
    __syncthreads();
#pragma unroll
    for (int pass = 3; pass >= 0; pass--) {
        unsigned prefix = sh_prefix;
        int rank = sh_rank;
        hist[tid] = 0;
        __syncthreads();
        const int shv = pass * 8;
        const unsigned himask = (pass == 3) ? 0u : (0xffffffffu << ((shv + 8) & 31));
#pragma unroll
        for (int j = 0; j < 4; j++)
            if ((u[j] & himask) == prefix) atomicAdd(&hist[(u[j] >> shv) & 255], 1);
        __syncthreads();
        int c = hist[tid];
        int lane = tid & 31, wid = tid >> 5;
        int x = c;
#pragma unroll
        for (int o = 1; o < 32; o <<= 1) {
            int y = __shfl_up_sync(0xffffffffu, x, o);
            if (lane >= o) x += y;
        }
        if (lane == 31) wred[wid] = x;
        __syncthreads();
        int wofs = 0;
#pragma unroll
        for (int w = 0; w < 8; w++) if (w < wid) wofs += wred[w];
        int incl = x + wofs;
        int excl = incl - c;
        if (rank >= excl && rank < incl) {
            sh_prefix = prefix | ((unsigned)tid << shv);
            sh_rank = rank - excl;
        }
        __syncthreads();
    }
    unsigned u818 = sh_prefix;
    // count(<= u818) and min key strictly greater (for order stat 819)
    int cl = 0; unsigned mg = 0xffffffffu;
#pragma unroll
    for (int j = 0; j < 4; j++) {
        cl += (u[j] <= u818) ? 1 : 0;
        if (u[j] > u818) mg = min(mg, u[j]);
    }
    {
        int lane = tid & 31;
#pragma unroll
        for (int o = 16; o > 0; o >>= 1) {
            cl += __shfl_down_sync(0xffffffffu, cl, o);
            unsigned og = __shfl_down_sync(0xffffffffu, mg, o);
            mg = min(mg, og);
        }
        if (lane == 0) { atomicAdd(&sh_cle, cl); atomicMin(&sh_mg, mg); }
        __syncthreads();
    }
    unsigned u819 = (sh_cle >= 820) ? u818 : sh_mg;
    float v818 = key2f(u818), v819 = key2f(u819);
    // match jnp.quantile 'linear': idx = q*(n-1) in f32; out = lo*lw + hi*hw
    float qi = __fmul_rn(0.8f, 1023.0f);
    float hw = __fsub_rn(qi, 818.0f);
    float lw = __fsub_rn(1.0f, hw);
    float nps = __fadd_rn(__fmul_rn(v818, lw), __fmul_rn(v819, hw));

    unsigned long long* nbits = g_bits[cur ^ 1];
#pragma unroll
    for (int j = 0; j < 4; j++) {
        int r = (tid + j * 256) * 5 + kq;
        int idx = base + r;
        float m = v[j] - nps;
        m = m > 0.f ? m : 0.f;
        g_mem[idx] = m;
        float ttr = g_ttr[idx];
        float thr = 0.5f + thb[r] * ttr;
        float spk = (m - thr) > 0.f ? 1.f : 0.f;
        float thd = fminf(fmaxf(thdp[r], 0.f), 1.f);
        float rfd = fminf(fmaxf(rfdp[r], 0.f), 1.f);
        float cud = fminf(fmaxf(cudp[r], 0.f), 1.f);
        g_ttr[idx] = ttr * thd + spk;
        g_rtr[idx] = g_rtr[idx] * rfd + spk;
        g_ctr[idx] = g_ctr[idx] * cud + spk;
        if (spk != 0.f) {
            g_ssum[idx] += 1.f;
            atomicOr(&nbits[r], 1ull << b);
        }
    }
}

// ---------------- compaction of active neurons (deterministic ascending) ----------------
__global__ void __launch_bounds__(1024) k_compact(int next)
{
    __shared__ int wsum[32];
    int tid = threadIdx.x;
    const unsigned long long* bits = g_bits[next];
    int r0 = tid * 5;
    unsigned long long mloc[5];
    int cnt = 0;
#pragma unroll
    for (int j = 0; j < 5; j++) { mloc[j] = bits[r0 + j]; cnt += (mloc[j] != 0ull) ? 1 : 0; }
    int lane = tid & 31, wid = tid >> 5;
    int x = cnt;
#pragma unroll
    for (int o = 1; o < 32; o <<= 1) {
        int y = __shfl_up_sync(0xffffffffu, x, o);
        if (lane >= o) x += y;
    }
    if (lane == 31) wsum[wid] = x;
    __syncthreads();
    if (wid == 0) {
        int v = wsum[lane];
#pragma unroll
        for (int o = 1; o < 32; o <<= 1) {
            int y = __shfl_up_sync(0xffffffffu, v, o);
            if (lane >= o) v += y;
        }
        wsum[lane] = v;
    }
    __syncthreads();
    int basei = (wid ? wsum[wid - 1] : 0) + x - cnt;
#pragma unroll
    for (int j = 0; j < 5; j++)
        if (mloc[j]) g_act[basei++] = r0 + j;
    if (tid == 1023) g_nact = basei;
    // zero the consumed (old) buffer for reuse as target two steps later
    unsigned long long* ob = g_bits[next ^ 1];
#pragma unroll
    for (int j = 0; j < 5; j++) ob[r0 + j] = 0ull;
}

// ---------------- readout ----------------
__global__ void __launch_bounds__(256) k_out(const float* __restrict__ Wm,
                                             const float* __restrict__ bm,
                                             float* __restrict__ out)
{
    int b = blockIdx.x;
    __shared__ float row[Rn];
    for (int i = threadIdx.x; i < Rn; i += 256) row[i] = g_ssum[b * Rn + i] * (1.0f / 24.0f);
    __syncthreads();
    int wid = threadIdx.x >> 5, lane = threadIdx.x & 31;
    for (int c = wid; c < Cn; c += 8) {
        float s = 0.f;
        for (int i = lane; i < Rn; i += 32) s += row[i] * Wm[c * Rn + i];
#pragma unroll
        for (int o = 16; o > 0; o >>= 1) s += __shfl_down_sync(0xffffffffu, s, o);
        if (lane == 0) out[b * Cn + c] = s + bm[c];
    }
}

extern "C" void kernel_launch(void* const* d_in, const int* in_sizes, int n_in,
                              void* d_out, int out_size)
{
    const float* x      = (const float*)d_in[0];
    const float* ln_g   = (const float*)d_in[1];
    const float* ln_b   = (const float*)d_in[2];
    const float* Wp     = (const float*)d_in[3];
    const float* bp     = (const float*)d_in[4];
    const float* Wl     = (const float*)d_in[5];
    const float* bl     = (const float*)d_in[6];
    const float* Wm     = (const float*)d_in[7];
    const float* bm     = (const float*)d_in[8];
    const float* decay  = (const float*)d_in[9];
    const float* thrb   = (const float*)d_in[10];
    const float* thrd   = (const float*)d_in[11];
    const float* refb   = (const float*)d_in[12];
    const float* refd   = (const float*)d_in[13];
    const float* curb   = (const float*)d_in[14];
    const float* curd   = (const float*)d_in[15];
    const float* latm   = (const float*)d_in[17];
    float* out = (float*)d_out;

    k_init<<<1280, 256>>>();
    k_prepW<<<dim3(160, 160), dim3(32, 8)>>>(Wl, latm);
    k_ln<<<Tn * Bn, 256>>>(x, ln_g, ln_b);
    k_drive<<<dim3(40, 12), 256>>>(Wp, bp);
    for (int t = 0; t < Tn; t++) {
        int cur = t & 1;
        k_rec<<<dim3(20, NSPLIT), 256>>>(cur);
        k_s1<<<1280, 256>>>(cur, t, bl, decay, refb, curb);
        k_s2<<<dim3(Bn, 5), 256>>>(cur, thrb, thrd, refd, curd);
        k_compact<<<1, 1024>>>(cur ^ 1);
    }
    k_out<<<Bn, 256>>>(Wm, bm, out);
}

// round 3
// speedup vs baseline: 1.2613x; 1.2613x over previous
#include <cuda_runtime.h>

#define Tn 24
#define Bn 64
#define Dn 1536
#define Rn 5120
#define Cn 100
#define NSPLIT 16

__device__ float g_WlT[Rn * Rn];             // [r'][r] = Wl[r][r']*lat_mask[r][r']
__device__ float g_xn[Tn * Bn * Dn];
__device__ float g_drive[Tn * Bn * Rn];
__device__ float g_mem[Bn * Rn];
__device__ float g_ttr[Bn * Rn];
__device__ float g_rtr[Bn * Rn];
__device__ float g_ctr[Bn * Rn];
__device__ float g_ssum[Bn * Rn];
__device__ float g_mempre[Bn * Rn];
__device__ float g_partial[NSPLIT][Bn * Rn];
__device__ unsigned long long g_bits[2][Rn]; // bit b of g_bits[cur][r] = spike(b, r)
__device__ int g_act[Rn];
__device__ int g_nact;
__device__ int g_sync;

// ---------------- init ----------------
__global__ void k_init()
{
    int i = blockIdx.x * 256 + threadIdx.x;
    if (i < Bn * Rn) {
        g_mem[i] = 0.f; g_ttr[i] = 0.f; g_rtr[i] = 0.f; g_ctr[i] = 0.f; g_ssum[i] = 0.f;
    }
    if (i < Rn) { g_bits[0][i] = 0ull; g_bits[1][i] = 0ull; }
    if (i == 0) { g_nact = 0; g_sync = 0; }
}

// ---------------- masked transpose of Wl ----------------
__global__ void k_prepW(const float* __restrict__ Wl, const float* __restrict__ lm)
{
    __shared__ float tile[32][33];
    int bx = blockIdx.x * 32;  // r' (col of Wl)
    int by = blockIdx.y * 32;  // r  (row of Wl)
    int x = bx + threadIdx.x;
#pragma unroll
    for (int j = 0; j < 32; j += 8) {
        int y = by + threadIdx.y + j;
        tile[threadIdx.y + j][threadIdx.x] = Wl[y * Rn + x] * lm[y * Rn + x];
    }
    __syncthreads();
    int xo = by + threadIdx.x;  // r
#pragma unroll
    for (int j = 0; j < 32; j += 8) {
        int yo = bx + threadIdx.y + j;  // r'
        g_WlT[yo * Rn + xo] = tile[threadIdx.x][threadIdx.y + j];
    }
}

// ---------------- layernorm ----------------
__global__ void __launch_bounds__(256) k_ln(const float* __restrict__ x,
                                            const float* __restrict__ gw,
                                            const float* __restrict__ gb)
{
    const int row = blockIdx.x;
    const float* xr = x + row * Dn;
    float s = 0.f, s2 = 0.f;
    for (int i = threadIdx.x; i < Dn; i += 256) { float v = xr[i]; s += v; s2 += v * v; }
    __shared__ float sh[64];
    int lane = threadIdx.x & 31, wid = threadIdx.x >> 5;
#pragma unroll
    for (int o = 16; o > 0; o >>= 1) {
        s += __shfl_down_sync(0xffffffffu, s, o);
        s2 += __shfl_down_sync(0xffffffffu, s2, o);
    }
    if (lane == 0) { sh[wid] = s; sh[wid + 32] = s2; }
    __syncthreads();
    if (threadIdx.x == 0) {
        float ts = 0.f, ts2 = 0.f;
        for (int w = 0; w < 8; w++) { ts += sh[w]; ts2 += sh[w + 32]; }
        float mean = ts * (1.0f / Dn);
        float var = ts2 * (1.0f / Dn) - mean * mean;
        sh[0] = mean;
        sh[1] = rsqrtf(var + 1e-5f);
    }
    __syncthreads();
    float mean = sh[0], inv = sh[1];
    for (int i = threadIdx.x; i < Dn; i += 256)
        g_xn[row * Dn + i] = (xr[i] - mean) * inv * gw[i] + gb[i];
}

// ---------------- block-structured drive GEMM ----------------
__global__ void __launch_bounds__(256) k_drive(const float* __restrict__ Wp,
                                               const float* __restrict__ bp)
{
    __shared__ float As[16][128];
    __shared__ float Bs[16][128];
    const int bn = blockIdx.x, bm = blockIdx.y;
    const int nb = (bn * 128) >> 10;  // neuron block 0..4
    const int koff_t[5] = {0, 512, 1024, 1280, 1408};
    const int klen_t[5] = {512, 512, 256, 128, 0};
    const int k0 = koff_t[nb], kl = klen_t[nb];
    const int tid = threadIdx.x;
    const int tx = tid & 15, ty = tid >> 4;
    float acc[8][8];
#pragma unroll
    for (int i = 0; i < 8; i++)
#pragma unroll
        for (int j = 0; j < 8; j++) acc[i][j] = 0.f;

    const int ldm = tid >> 2;
    const int ldk = (tid & 3) << 2;
    for (int kt = 0; kt < kl; kt += 16) {
#pragma unroll
        for (int h = 0; h < 2; h++) {
            int m = ldm + h * 64;
            float4 av = *(const float4*)&g_xn[(bm * 128 + m) * Dn + k0 + kt + ldk];
            As[ldk + 0][m] = av.x; As[ldk + 1][m] = av.y; As[ldk + 2][m] = av.z; As[ldk + 3][m] = av.w;
            float4 bv = *(const float4*)&Wp[(bn * 128 + m) * Dn + k0 + kt + ldk];
            Bs[ldk + 0][m] = bv.x; Bs[ldk + 1][m] = bv.y; Bs[ldk + 2][m] = bv.z; Bs[ldk + 3][m] = bv.w;
        }
        __syncthreads();
#pragma unroll
        for (int k = 0; k < 16; k++) {
            float a[8], b[8];
#pragma unroll
            for (int i = 0; i < 8; i++) a[i] = As[k][ty * 8 + i];
#pragma unroll
            for (int j = 0; j < 8; j++) b[j] = Bs[k][tx * 8 + j];
#pragma unroll
            for (int i = 0; i < 8; i++)
#pragma unroll
                for (int j = 0; j < 8; j++) acc[i][j] += a[i] * b[j];
        }
        __syncthreads();
    }
#pragma unroll
    for (int i = 0; i < 8; i++) {
        int row = bm * 128 + ty * 8 + i;
#pragma unroll
        for (int j = 0; j < 8; j++) {
            int col = bn * 128 + tx * 8 + j;
            g_drive[row * Rn + col] = acc[i][j] + bp[col];
        }
    }
}

// ---------------- lateral recurrence: packed f32x2 predicated adds ----------------
// thread -> 2 adjacent columns; blockIdx.z -> batch half (32 batches); blockIdx.y -> split of act list
__global__ void __launch_bounds__(256) k_rec(int cur)
{
    const int tid = threadIdx.x;
    const int col2 = blockIdx.x * 256 + tid;       // pair index 0..2559
    const int split = blockIdx.y;                  // 0..15
    const int half = blockIdx.z;                   // 0..1
    const int total = g_nact;
    const int per = (total + NSPLIT - 1) / NSPLIT; // <= 320
    int i0 = split * per;
    int i1 = i0 + per; if (i1 > total) i1 = total;
    const int n = i1 - i0;

    __shared__ int s_act[320];
    __shared__ unsigned s_mb[320];
    const unsigned long long* __restrict__ bits = g_bits[cur];
    for (int i = tid; i < n; i += 256) {
        int a = g_act[i0 + i];
        s_act[i] = a;
        s_mb[i] = (unsigned)(bits[a] >> (half * 32));
    }
    __syncthreads();

    unsigned long long acc[32];
#pragma unroll
    for (int j = 0; j < 32; j++) acc[j] = 0ull;

    const unsigned long long* __restrict__ W = (const unsigned long long*)g_WlT;
#pragma unroll 2
    for (int i = 0; i < n; i++) {
        int rp = s_act[i];
        unsigned mb = s_mb[i];
        unsigned long long wp = __ldg(&W[(size_t)rp * (Rn / 2) + col2]);
#pragma unroll
        for (int j = 0; j < 32; j++) {
            asm("{\n\t"
                ".reg .pred p;\n\t"
                "setp.ne.u32 p, %2, 0;\n\t"
                "@p add.rn.f32x2 %0, %0, %1;\n\t"
                "}"
                : "+l"(acc[j]) : "l"(wp), "r"(mb & (1u << j)));
        }
    }

    unsigned long long* out = (unsigned long long*)&g_partial[split][0];
#pragma unroll
    for (int j = 0; j < 32; j++)
        out[(size_t)(half * 32 + j) * (Rn / 2) + col2] = acc[j];
}

// ---------------- elementwise pre-WTA membrane (float4) ----------------
__global__ void __launch_bounds__(256) k_s1(int cur, int t,
                                            const float* __restrict__ bl,
                                            const float* __restrict__ decp,
                                            const float* __restrict__ refb,
                                            const float* __restrict__ curb)
{
    int idx = (blockIdx.x * 256 + threadIdx.x) * 4;
    int r = idx % Rn;
    int b = idx / Rn;
    float4 p = make_float4(0.f, 0.f, 0.f, 0.f);
#pragma unroll
    for (int s = 0; s < NSPLIT; s++) {
        float4 q = *(const float4*)&g_partial[s][idx];
        p.x += q.x; p.y += q.y; p.z += q.z; p.w += q.w;
    }
    float4 mem = *(const float4*)&g_mem[idx];
    float4 rtr = *(const float4*)&g_rtr[idx];
    float4 ctr = *(const float4*)&g_ctr[idx];
    float4 dr  = *(const float4*)&g_drive[t * (Bn * Rn) + idx];
    float4 dec = *(const float4*)&decp[r];
    float4 rb  = *(const float4*)&refb[r];
    float4 cb  = *(const float4*)&curb[r];
    float4 blv = *(const float4*)&bl[r];
    const unsigned long long* bits = g_bits[cur];
    float4 o;
    {
        float spk = (float)((bits[r + 0] >> b) & 1ull);
        float d = fminf(fmaxf(dec.x, 0.f), 1.f);
        o.x = (mem.x - spk * (0.5f + rb.x * rtr.x)) * d + (dr.x + p.x + blv.x) + cb.x * ctr.x;
    }
    {
        float spk = (float)((bits[r + 1] >> b) & 1ull);
        float d = fminf(fmaxf(dec.y, 0.f), 1.f);
        o.y = (mem.y - spk * (0.5f + rb.y * rtr.y)) * d + (dr.y + p.y + blv.y) + cb.y * ctr.y;
    }
    {
        float spk = (float)((bits[r + 2] >> b) & 1ull);
        float d = fminf(fmaxf(dec.z, 0.f), 1.f);
        o.z = (mem.z - spk * (0.5f + rb.z * rtr.z)) * d + (dr.z + p.z + blv.z) + cb.z * ctr.z;
    }
    {
        float spk = (float)((bits[r + 3] >> b) & 1ull);
        float d = fminf(fmaxf(dec.w, 0.f), 1.f);
        o.w = (mem.w - spk * (0.5f + rb.w * rtr.w)) * d + (dr.w + p.w + blv.w) + cb.w * ctr.w;
    }
    *(float4*)&g_mempre[idx] = o;
}

// ---------------- WTA quantile + spike + traces + fused compaction ----------------
__device__ __forceinline__ unsigned f2key(float f)
{
    unsigned b = __float_as_uint(f);
    return (b & 0x80000000u) ? ~b : (b | 0x80000000u);
}
__device__ __forceinline__ float key2f(unsigned u)
{
    unsigned b = (u & 0x80000000u) ? (u & 0x7fffffffu) : ~u;
    return __uint_as_float(b);
}

__global__ void __launch_bounds__(256) k_s2(int cur,
                                            const float* __restrict__ thb,
                                            const float* __restrict__ thdp,
                                            const float* __restrict__ rfdp,
                                            const float* __restrict__ cudp)
{
    const int b = blockIdx.x, kq = blockIdx.y;
    const int tid = threadIdx.x;
    __shared__ int hist[256];
    __shared__ int wred[8];
    __shared__ int sh_rank;
    __shared__ unsigned sh_prefix;
    __shared__ int sh_cle;
    __shared__ unsigned sh_mg;

    float v[4]; unsigned u[4];
    const int base = b * Rn;
#pragma unroll
    for (int j = 0; j < 4; j++) {
        int r = (tid + j * 256) * 5 + kq;
        v[j] = g_mempre[base + r];
        u[j] = f2key(v[j]);
    }
    if (tid == 0) { sh_prefix = 0u; sh_rank = 818; sh_cle = 0; sh_mg = 0xffffffffu; }
    __syncthreads();
#pragma unroll
    for (int pass = 3; pass >= 0; pass--) {
        unsigned prefix = sh_prefix;
        int rank = sh_rank;
        hist[tid] = 0;
        __syncthreads();
        const int shv = pass * 8;
        const unsigned himask = (pass == 3) ? 0u : (0xffffffffu << ((shv + 8) & 31));
#pragma unroll
        for (int j = 0; j < 4; j++)
            if ((u[j] & himask) == prefix) atomicAdd(&hist[(u[j] >> shv) & 255], 1);
        __syncthreads();
        int c = hist[tid];
        int lane = tid & 31, wid = tid >> 5;
        int x = c;
#pragma unroll
        for (int o = 1; o < 32; o <<= 1) {
            int y = __shfl_up_sync(0xffffffffu, x, o);
            if (lane >= o) x += y;
        }
        if (lane == 31) wred[wid] = x;
        __syncthreads();
        int wofs = 0;
#pragma unroll
        for (int w = 0; w < 8; w++) if (w < wid) wofs += wred[w];
        int incl = x + wofs;
        int excl = incl - c;
        if (rank >= excl && rank < incl) {
            sh_prefix = prefix | ((unsigned)tid << shv);
            sh_rank = rank - excl;
        }
        __syncthreads();
    }
    unsigned u818 = sh_prefix;
    int cl = 0; unsigned mg = 0xffffffffu;
#pragma unroll
    for (int j = 0; j < 4; j++) {
        cl += (u[j] <= u818) ? 1 : 0;
        if (u[j] > u818) mg = min(mg, u[j]);
    }
    {
        int lane = tid & 31;
#pragma unroll
        for (int o = 16; o > 0; o >>= 1) {
            cl += __shfl_down_sync(0xffffffffu, cl, o);
            unsigned og = __shfl_down_sync(0xffffffffu, mg, o);
            mg = min(mg, og);
        }
        if (lane == 0) { atomicAdd(&sh_cle, cl); atomicMin(&sh_mg, mg); }
        __syncthreads();
    }
    unsigned u819 = (sh_cle >= 820) ? u818 : sh_mg;
    float v818 = key2f(u818), v819 = key2f(u819);
    // match jnp.quantile 'linear': idx = q*(n-1) in f32; out = lo*lw + hi*hw
    float qi = __fmul_rn(0.8f, 1023.0f);
    float hw = __fsub_rn(qi, 818.0f);
    float lw = __fsub_rn(1.0f, hw);
    float nps = __fadd_rn(__fmul_rn(v818, lw), __fmul_rn(v819, hw));

    unsigned long long* nbits = g_bits[cur ^ 1];
#pragma unroll
    for (int j = 0; j < 4; j++) {
        int r = (tid + j * 256) * 5 + kq;
        int idx = base + r;
        float m = v[j] - nps;
        m = m > 0.f ? m : 0.f;
        g_mem[idx] = m;
        float ttr = g_ttr[idx];
        float thr = 0.5f + thb[r] * ttr;
        float spk = (m - thr) > 0.f ? 1.f : 0.f;
        float thd = fminf(fmaxf(thdp[r], 0.f), 1.f);
        float rfd = fminf(fmaxf(rfdp[r], 0.f), 1.f);
        float cud = fminf(fmaxf(cudp[r], 0.f), 1.f);
        g_ttr[idx] = ttr * thd + spk;
        g_rtr[idx] = g_rtr[idx] * rfd + spk;
        g_ctr[idx] = g_ctr[idx] * cud + spk;
        if (spk != 0.f) {
            g_ssum[idx] += 1.f;
            atomicOr(&nbits[r], 1ull << b);
        }
    }

    // ---- fused compaction: last of the 320 blocks compacts the new bitmask ----
    __threadfence();
    __shared__ int isLast;
    if (tid == 0) isLast = (atomicAdd(&g_sync, 1) == (Bn * 5 - 1)) ? 1 : 0;
    __syncthreads();
    if (!isLast) return;
    __threadfence();

    const unsigned long long* nb = g_bits[cur ^ 1];
    unsigned long long* ob = g_bits[cur];
    const int r0c = tid * 20;
    int cnt = 0;
#pragma unroll
    for (int j = 0; j < 20; j++) cnt += (nb[r0c + j] != 0ull) ? 1 : 0;
    int lane = tid & 31, wid = tid >> 5;
    int x = cnt;
#pragma unroll
    for (int o = 1; o < 32; o <<= 1) {
        int y = __shfl_up_sync(0xffffffffu, x, o);
        if (lane >= o) x += y;
    }
    if (lane == 31) wred[wid] = x;
    __syncthreads();
    int wofs = 0;
#pragma unroll
    for (int w = 0; w < 8; w++) if (w < wid) wofs += wred[w];
    int pos = wofs + x - cnt;
#pragma unroll
    for (int j = 0; j < 20; j++)
        if (nb[r0c + j] != 0ull) g_act[pos++] = r0c + j;
    if (tid == 255) g_nact = pos;
#pragma unroll
    for (int j = 0; j < 20; j++) ob[r0c + j] = 0ull;  // clear consumed buffer
    if (tid == 0) g_sync = 0;
}

// ---------------- readout ----------------
__global__ void __launch_bounds__(256) k_out(const float* __restrict__ Wm,
                                             const float* __restrict__ bm,
                                             float* __restrict__ out)
{
    int b = blockIdx.x;
    __shared__ float row[Rn];
    for (int i = threadIdx.x; i < Rn; i += 256) row[i] = g_ssum[b * Rn + i] * (1.0f / 24.0f);
    __syncthreads();
    int wid = threadIdx.x >> 5, lane = threadIdx.x & 31;
    for (int c = wid; c < Cn; c += 8) {
        float s = 0.f;
        for (int i = lane; i < Rn; i += 32) s += row[i] * Wm[c * Rn + i];
#pragma unroll
        for (int o = 16; o > 0; o >>= 1) s += __shfl_down_sync(0xffffffffu, s, o);
        if (lane == 0) out[b * Cn + c] = s + bm[c];
    }
}

extern "C" void kernel_launch(void* const* d_in, const int* in_sizes, int n_in,
                              void* d_out, int out_size)
{
    const float* x      = (const float*)d_in[0];
    const float* ln_g   = (const float*)d_in[1];
    const float* ln_b   = (const float*)d_in[2];
    const float* Wp     = (const float*)d_in[3];
    const float* bp     = (const float*)d_in[4];
    const float* Wl     = (const float*)d_in[5];
    const float* bl     = (const float*)d_in[6];
    const float* Wm     = (const float*)d_in[7];
    const float* bm     = (const float*)d_in[8];
    const float* decay  = (const float*)d_in[9];
    const float* thrb   = (const float*)d_in[10];
    const float* thrd   = (const float*)d_in[11];
    const float* refb   = (const float*)d_in[12];
    const float* refd   = (const float*)d_in[13];
    const float* curb   = (const float*)d_in[14];
    const float* curd   = (const float*)d_in[15];
    const float* latm   = (const float*)d_in[17];
    float* out = (float*)d_out;

    k_init<<<1280, 256>>>();
    k_prepW<<<dim3(160, 160), dim3(32, 8)>>>(Wl, latm);
    k_ln<<<Tn * Bn, 256>>>(x, ln_g, ln_b);
    k_drive<<<dim3(40, 12), 256>>>(Wp, bp);
    for (int t = 0; t < Tn; t++) {
        int cur = t & 1;
        k_rec<<<dim3(10, NSPLIT, 2), 256>>>(cur);
        k_s1<<<320, 256>>>(cur, t, bl, decay, refb, curb);
        k_s2<<<dim3(Bn, 5), 256>>>(cur, thrb, thrd, refd, curd);
    }
    k_out<<<Bn, 256>>>(Wm, bm, out);
}

// round 5
// speedup vs baseline: 1.3083x; 1.0373x over previous
#include <cuda_runtime.h>

#define Tn 24
#define Bn 64
#define Dn 1536
#define Rn 5120
#define Cn 100
#define NSPLIT 16
#define MAXPER 320   // ceil(Rn / NSPLIT)

__device__ float g_WlT[Rn * Rn];             // [r'][r] = Wl[r][r']*lat_mask[r][r']
__device__ float g_xn[Tn * Bn * Dn];
__device__ float g_drive[Tn * Bn * Rn];
__device__ float g_mem[Bn * Rn];
__device__ float g_ttr[Bn * Rn];
__device__ float g_rtr[Bn * Rn];
__device__ float g_ctr[Bn * Rn];
__device__ float g_ssum[Bn * Rn];
__device__ float g_mempre[Bn * Rn];
__device__ float g_partial[NSPLIT][Bn * Rn];
__device__ unsigned long long g_bits[2][Rn]; // bit b of g_bits[cur][r] = spike(b, r)
__device__ int g_act[Rn];
__device__ int g_nact;
__device__ int g_sync;

// ---------------- init ----------------
__global__ void k_init()
{
    int i = blockIdx.x * 256 + threadIdx.x;
    if (i < Bn * Rn) {
        g_mem[i] = 0.f; g_ttr[i] = 0.f; g_rtr[i] = 0.f; g_ctr[i] = 0.f; g_ssum[i] = 0.f;
    }
    if (i < Rn) { g_bits[0][i] = 0ull; g_bits[1][i] = 0ull; }
    if (i == 0) { g_nact = 0; g_sync = 0; }
}

// ---------------- masked transpose of Wl ----------------
__global__ void k_prepW(const float* __restrict__ Wl, const float* __restrict__ lm)
{
    __shared__ float tile[32][33];
    int bx = blockIdx.x * 32;  // r' (col of Wl)
    int by = blockIdx.y * 32;  // r  (row of Wl)
    int x = bx + threadIdx.x;
#pragma unroll
    for (int j = 0; j < 32; j += 8) {
        int y = by + threadIdx.y + j;
        tile[threadIdx.y + j][threadIdx.x] = Wl[y * Rn + x] * lm[y * Rn + x];
    }
    __syncthreads();
    int xo = by + threadIdx.x;  // r
#pragma unroll
    for (int j = 0; j < 32; j += 8) {
        int yo = bx + threadIdx.y + j;  // r'
        g_WlT[yo * Rn + xo] = tile[threadIdx.x][threadIdx.y + j];
    }
}

// ---------------- layernorm ----------------
__global__ void __launch_bounds__(256) k_ln(const float* __restrict__ x,
                                            const float* __restrict__ gw,
                                            const float* __restrict__ gb)
{
    const int row = blockIdx.x;
    const float* xr = x + row * Dn;
    float s = 0.f, s2 = 0.f;
    for (int i = threadIdx.x; i < Dn; i += 256) { float v = xr[i]; s += v; s2 += v * v; }
    __shared__ float sh[64];
    int lane = threadIdx.x & 31, wid = threadIdx.x >> 5;
#pragma unroll
    for (int o = 16; o > 0; o >>= 1) {
        s += __shfl_down_sync(0xffffffffu, s, o);
        s2 += __shfl_down_sync(0xffffffffu, s2, o);
    }
    if (lane == 0) { sh[wid] = s; sh[wid + 32] = s2; }
    __syncthreads();
    if (threadIdx.x == 0) {
        float ts = 0.f, ts2 = 0.f;
        for (int w = 0; w < 8; w++) { ts += sh[w]; ts2 += sh[w + 32]; }
        float mean = ts * (1.0f / Dn);
        float var = ts2 * (1.0f / Dn) - mean * mean;
        sh[0] = mean;
        sh[1] = rsqrtf(var + 1e-5f);
    }
    __syncthreads();
    float mean = sh[0], inv = sh[1];
    for (int i = threadIdx.x; i < Dn; i += 256)
        g_xn[row * Dn + i] = (xr[i] - mean) * inv * gw[i] + gb[i];
}

// ---------------- block-structured drive GEMM ----------------
__global__ void __launch_bounds__(256) k_drive(const float* __restrict__ Wp,
                                               const float* __restrict__ bp)
{
    __shared__ float As[16][128];
    __shared__ float Bs[16][128];
    const int bn = blockIdx.x, bm = blockIdx.y;
    const int nb = (bn * 128) >> 10;  // neuron block 0..4
    const int koff_t[5] = {0, 512, 1024, 1280, 1408};
    const int klen_t[5] = {512, 512, 256, 128, 0};
    const int k0 = koff_t[nb], kl = klen_t[nb];
    const int tid = threadIdx.x;
    const int tx = tid & 15, ty = tid >> 4;
    float acc[8][8];
#pragma unroll
    for (int i = 0; i < 8; i++)
#pragma unroll
        for (int j = 0; j < 8; j++) acc[i][j] = 0.f;

    const int ldm = tid >> 2;
    const int ldk = (tid & 3) << 2;
    for (int kt = 0; kt < kl; kt += 16) {
#pragma unroll
        for (int h = 0; h < 2; h++) {
            int m = ldm + h * 64;
            float4 av = *(const float4*)&g_xn[(bm * 128 + m) * Dn + k0 + kt + ldk];
            As[ldk + 0][m] = av.x; As[ldk + 1][m] = av.y; As[ldk + 2][m] = av.z; As[ldk + 3][m] = av.w;
            float4 bv = *(const float4*)&Wp[(bn * 128 + m) * Dn + k0 + kt + ldk];
            Bs[ldk + 0][m] = bv.x; Bs[ldk + 1][m] = bv.y; Bs[ldk + 2][m] = bv.z; Bs[ldk + 3][m] = bv.w;
        }
        __syncthreads();
#pragma unroll
        for (int k = 0; k < 16; k++) {
            float a[8], b[8];
#pragma unroll
            for (int i = 0; i < 8; i++) a[i] = As[k][ty * 8 + i];
#pragma unroll
            for (int j = 0; j < 8; j++) b[j] = Bs[k][tx * 8 + j];
#pragma unroll
            for (int i = 0; i < 8; i++)
#pragma unroll
                for (int j = 0; j < 8; j++) acc[i][j] += a[i] * b[j];
        }
        __syncthreads();
    }
#pragma unroll
    for (int i = 0; i < 8; i++) {
        int row = bm * 128 + ty * 8 + i;
#pragma unroll
        for (int j = 0; j < 8; j++) {
            int col = bn * 128 + tx * 8 + j;
            g_drive[row * Rn + col] = acc[i][j] + bp[col];
        }
    }
}

// ---------------- lateral recurrence: packed f32x2 FFMA with 0/1 spike multipliers ----
// thread -> 2 adjacent columns; blockIdx.z -> batch half (32); blockIdx.y -> split of act list
__global__ void __launch_bounds__(256) k_rec(int cur)
{
    extern __shared__ char smraw[];
    float2* s_spk = (float2*)smraw;                       // [MAXPER][32] duplicated (s,s)
    int* s_act = (int*)(smraw + MAXPER * 32 * sizeof(float2));
    const int tid = threadIdx.x;
    const int col2 = blockIdx.x * 256 + tid;              // pair index 0..2559
    const int split = blockIdx.y;
    const int half = blockIdx.z;
    const int total = g_nact;
    const int per = (total + NSPLIT - 1) / NSPLIT;
    int i0 = split * per;
    int i1 = i0 + per; if (i1 > total) i1 = total;
    int n = i1 - i0; if (n < 0) n = 0;

    const unsigned long long* __restrict__ bits = g_bits[cur];
    for (int i = tid; i < n; i += 256) s_act[i] = g_act[i0 + i];
    for (int idx = tid; idx < n * 32; idx += 256) {
        int i = idx >> 5, j = idx & 31;
        int a = g_act[i0 + i];
        unsigned m = (unsigned)(bits[a] >> (half * 32));
        float s = (float)((m >> j) & 1u);
        s_spk[idx] = make_float2(s, s);
    }
    __syncthreads();

    unsigned long long acc[32];
#pragma unroll
    for (int j = 0; j < 32; j++) acc[j] = 0ull;

    const unsigned long long* __restrict__ W = (const unsigned long long*)g_WlT;
    unsigned long long wp = (n > 0) ? __ldg(&W[(size_t)s_act[0] * (Rn / 2) + col2]) : 0ull;
    for (int i = 0; i < n; i++) {
        unsigned long long wn = (i + 1 < n) ? __ldg(&W[(size_t)s_act[i + 1] * (Rn / 2) + col2]) : 0ull;
        const ulonglong2* sp = (const ulonglong2*)(s_spk + i * 32);
#pragma unroll
        for (int j = 0; j < 16; j++) {
            ulonglong2 q = sp[j];
            asm("fma.rn.f32x2 %0, %1, %2, %0;" : "+l"(acc[2 * j + 0]) : "l"(wp), "l"(q.x));
            asm("fma.rn.f32x2 %0, %1, %2, %0;" : "+l"(acc[2 * j + 1]) : "l"(wp), "l"(q.y));
        }
        wp = wn;
    }

    unsigned long long* out = (unsigned long long*)&g_partial[split][0];
#pragma unroll
    for (int j = 0; j < 32; j++)
        out[(size_t)(half * 32 + j) * (Rn / 2) + col2] = acc[j];
}

// ---------------- elementwise pre-WTA membrane (float4) ----------------
__global__ void __launch_bounds__(256) k_s1(int cur, int t,
                                            const float* __restrict__ bl,
                                            const float* __restrict__ decp,
                                            const float* __restrict__ refb,
                                            const float* __restrict__ curb)
{
    int idx = (blockIdx.x * 256 + threadIdx.x) * 4;
    int r = idx % Rn;
    int b = idx / Rn;
    float4 p = make_float4(0.f, 0.f, 0.f, 0.f);
#pragma unroll
    for (int s = 0; s < NSPLIT; s++) {
        float4 q = *(const float4*)&g_partial[s][idx];
        p.x += q.x; p.y += q.y; p.z += q.z; p.w += q.w;
    }
    float4 mem = *(const float4*)&g_mem[idx];
    float4 rtr = *(const float4*)&g_rtr[idx];
    float4 ctr = *(const float4*)&g_ctr[idx];
    float4 dr  = *(const float4*)&g_drive[t * (Bn * Rn) + idx];
    float4 dec = *(const float4*)&decp[r];
    float4 rb  = *(const float4*)&refb[r];
    float4 cb  = *(const float4*)&curb[r];
    float4 blv = *(const float4*)&bl[r];
    const unsigned long long* bits = g_bits[cur];
    float4 o;
    {
        float spk = (float)((bits[r + 0] >> b) & 1ull);
        float d = fminf(fmaxf(dec.x, 0.f), 1.f);
        o.x = (mem.x - spk * (0.5f + rb.x * rtr.x)) * d + (dr.x + p.x + blv.x) + cb.x * ctr.x;
    }
    {
        float spk = (float)((bits[r + 1] >> b) & 1ull);
        float d = fminf(fmaxf(dec.y, 0.f), 1.f);
        o.y = (mem.y - spk * (0.5f + rb.y * rtr.y)) * d + (dr.y + p.y + blv.y) + cb.y * ctr.y;
    }
    {
        float spk = (float)((bits[r + 2] >> b) & 1ull);
        float d = fminf(fmaxf(dec.z, 0.f), 1.f);
        o.z = (mem.z - spk * (0.5f + rb.z * rtr.z)) * d + (dr.z + p.z + blv.z) + cb.z * ctr.z;
    }
    {
        float spk = (float)((bits[r + 3] >> b) & 1ull);
        float d = fminf(fmaxf(dec.w, 0.f), 1.f);
        o.w = (mem.w - spk * (0.5f + rb.w * rtr.w)) * d + (dr.w + p.w + blv.w) + cb.w * ctr.w;
    }
    *(float4*)&g_mempre[idx] = o;
}

// ---------------- WTA quantile + spike + traces + fused compaction ----------------
__device__ __forceinline__ unsigned f2key(float f)
{
    unsigned b = __float_as_uint(f);
    return (b & 0x80000000u) ? ~b : (b | 0x80000000u);
}
__device__ __forceinline__ float key2f(unsigned u)
{
    unsigned b = (u & 0x80000000u) ? (u & 0x7fffffffu) : ~u;
    return __uint_as_float(b);
}

__global__ void __launch_bounds__(256) k_s2(int cur,
                                            const float* __restrict__ thb,
                                            const float* __restrict__ thdp,
                                            const float* __restrict__ rfdp,
                                            const float* __restrict__ cudp)
{
    const int b = blockIdx.x, kq = blockIdx.y;
    const int tid = threadIdx.x;
    __shared__ int hist[256];
    __shared__ int wred[8];
    __shared__ int sh_rank;
    __shared__ unsigned sh_prefix;
    __shared__ int sh_cle;
    __shared__ unsigned sh_mg;

    float v[4]; unsigned u[4];
    const int base = b * Rn;
#pragma unroll
    for (int j = 0; j < 4; j++) {
        int r = (tid + j * 256) * 5 + kq;
        v[j] = g_mempre[base + r];
        u[j] = f2key(v[j]);
    }
    if (tid == 0) { sh_prefix = 0u; sh_rank = 818; sh_cle = 0; sh_mg = 0xffffffffu; }
    __syncthreads();
#pragma unroll
    for (int pass = 3; pass >= 0; pass--) {
        unsigned prefix = sh_prefix;
        int rank = sh_rank;
        hist[tid] = 0;
        __syncthreads();
        const int shv = pass * 8;
        const unsigned himask = (pass == 3) ? 0u : (0xffffffffu << ((shv + 8) & 31));
#pragma unroll
        for (int j = 0; j < 4; j++)
            if ((u[j] & himask) == prefix) atomicAdd(&hist[(u[j] >> shv) & 255], 1);
        __syncthreads();
        int c = hist[tid];
        int lane = tid & 31, wid = tid >> 5;
        int x = c;
#pragma unroll
        for (int o = 1; o < 32; o <<= 1) {
            int y = __shfl_up_sync(0xffffffffu, x, o);
            if (lane >= o) x += y;
        }
        if (lane == 31) wred[wid] = x;
        __syncthreads();
        int wofs = 0;
#pragma unroll
        for (int w = 0; w < 8; w++) if (w < wid) wofs += wred[w];
        int incl = x + wofs;
        int excl = incl - c;
        if (rank >= excl && rank < incl) {
            sh_prefix = prefix | ((unsigned)tid << shv);
            sh_rank = rank - excl;
        }
        __syncthreads();
    }
    unsigned u818 = sh_prefix;
    int cl = 0; unsigned mg = 0xffffffffu;
#pragma unroll
    for (int j = 0; j < 4; j++) {
        cl += (u[j] <= u818) ? 1 : 0;
        if (u[j] > u818) mg = min(mg, u[j]);
    }
    {
        int lane = tid & 31;
#pragma unroll
        for (int o = 16; o > 0; o >>= 1) {
            cl += __shfl_down_sync(0xffffffffu, cl, o);
            unsigned og = __shfl_down_sync(0xffffffffu, mg, o);
            mg = min(mg, og);
        }
        if (lane == 0) { atomicAdd(&sh_cle, cl); atomicMin(&sh_mg, mg); }
        __syncthreads();
    }
    unsigned u819 = (sh_cle >= 820) ? u818 : sh_mg;
    float v818 = key2f(u818), v819 = key2f(u819);
    // match jnp.quantile 'linear': idx = q*(n-1) in f32; out = lo*lw + hi*hw
    float qi = __fmul_rn(0.8f, 1023.0f);
    float hw = __fsub_rn(qi, 818.0f);
    float lw = __fsub_rn(1.0f, hw);
    float nps = __fadd_rn(__fmul_rn(v818, lw), __fmul_rn(v819, hw));

    unsigned long long* nbits = g_bits[cur ^ 1];
#pragma unroll
    for (int j = 0; j < 4; j++) {
        int r = (tid + j * 256) * 5 + kq;
        int idx = base + r;
        float m = v[j] - nps;
        m = m > 0.f ? m : 0.f;
        g_mem[idx] = m;
        float ttr = g_ttr[idx];
        float thr = 0.5f + thb[r] * ttr;
        float spk = (m - thr) > 0.f ? 1.f : 0.f;
        float thd = fminf(fmaxf(thdp[r], 0.f), 1.f);
        float rfd = fminf(fmaxf(rfdp[r], 0.f), 1.f);
        float cud = fminf(fmaxf(cudp[r], 0.f), 1.f);
        g_ttr[idx] = ttr * thd + spk;
        g_rtr[idx] = g_rtr[idx] * rfd + spk;
        g_ctr[idx] = g_ctr[idx] * cud + spk;
        if (spk != 0.f) {
            g_ssum[idx] += 1.f;
            atomicOr(&nbits[r], 1ull << b);
        }
    }

    // ---- fused compaction: last of the 320 blocks compacts the new bitmask ----
    __threadfence();
    __shared__ int isLast;
    if (tid == 0) isLast = (atomicAdd(&g_sync, 1) == (Bn * 5 - 1)) ? 1 : 0;
    __syncthreads();
    if (!isLast) return;
    __threadfence();

    const unsigned long long* nb = g_bits[cur ^ 1];
    unsigned long long* ob = g_bits[cur];
    const int r0c = tid * 20;
    int cnt = 0;
#pragma unroll
    for (int j = 0; j < 20; j++) cnt += (nb[r0c + j] != 0ull) ? 1 : 0;
    int lane = tid & 31, wid = tid >> 5;
    int x = cnt;
#pragma unroll
    for (int o = 1; o < 32; o <<= 1) {
        int y = __shfl_up_sync(0xffffffffu, x, o);
        if (lane >= o) x += y;
    }
    if (lane == 31) wred[wid] = x;
    __syncthreads();
    int wofs = 0;
#pragma unroll
    for (int w = 0; w < 8; w++) if (w < wid) wofs += wred[w];
    int pos = wofs + x - cnt;
#pragma unroll
    for (int j = 0; j < 20; j++)
        if (nb[r0c + j] != 0ull) g_act[pos++] = r0c + j;
    if (tid == 255) g_nact = pos;
#pragma unroll
    for (int j = 0; j < 20; j++) ob[r0c + j] = 0ull;  // clear consumed buffer
    if (tid == 0) g_sync = 0;
}

// ---------------- readout ----------------
__global__ void __launch_bounds__(256) k_out(const float* __restrict__ Wm,
                                             const float* __restrict__ bm,
                                             float* __restrict__ out)
{
    int b = blockIdx.x;
    __shared__ float row[Rn];
    for (int i = threadIdx.x; i < Rn; i += 256) row[i] = g_ssum[b * Rn + i] * (1.0f / 24.0f);
    __syncthreads();
    int wid = threadIdx.x >> 5, lane = threadIdx.x & 31;
    for (int c = wid; c < Cn; c += 8) {
        float s = 0.f;
        for (int i = lane; i < Rn; i += 32) s += row[i] * Wm[c * Rn + i];
#pragma unroll
        for (int o = 16; o > 0; o >>= 1) s += __shfl_down_sync(0xffffffffu, s, o);
        if (lane == 0) out[b * Cn + c] = s + bm[c];
    }
}

extern "C" void kernel_launch(void* const* d_in, const int* in_sizes, int n_in,
                              void* d_out, int out_size)
{
    const float* x      = (const float*)d_in[0];
    const float* ln_g   = (const float*)d_in[1];
    const float* ln_b   = (const float*)d_in[2];
    const float* Wp     = (const float*)d_in[3];
    const float* bp     = (const float*)d_in[4];
    const float* Wl     = (const float*)d_in[5];
    const float* bl     = (const float*)d_in[6];
    const float* Wm     = (const float*)d_in[7];
    const float* bm     = (const float*)d_in[8];
    const float* decay  = (const float*)d_in[9];
    const float* thrb   = (const float*)d_in[10];
    const float* thrd   = (const float*)d_in[11];
    const float* refb   = (const float*)d_in[12];
    const float* refd   = (const float*)d_in[13];
    const float* curb   = (const float*)d_in[14];
    const float* curd   = (const float*)d_in[15];
    const float* latm   = (const float*)d_in[17];
    float* out = (float*)d_out;

    const int smemRec = MAXPER * 32 * sizeof(float2) + MAXPER * sizeof(int);
    cudaFuncSetAttribute(k_rec, cudaFuncAttributeMaxDynamicSharedMemorySize, smemRec);

    k_init<<<1280, 256>>>();
    k_prepW<<<dim3(160, 160), dim3(32, 8)>>>(Wl, latm);
    k_ln<<<Tn * Bn, 256>>>(x, ln_g, ln_b);
    k_drive<<<dim3(40, 12), 256>>>(Wp, bp);
    for (int t = 0; t < Tn; t++) {
        int cur = t & 1;
        k_rec<<<dim3(10, NSPLIT, 2), 256, smemRec>>>(cur);
        k_s1<<<320, 256>>>(cur, t, bl, decay, refb, curb);
        k_s2<<<dim3(Bn, 5), 256>>>(cur, thrb, thrd, refd, curd);
    }
    k_out<<<Bn, 256>>>(Wm, bm, out);
}

// round 6
// speedup vs baseline: 1.8779x; 1.4353x over previous
#include <cuda_runtime.h>
#include <cuda_bf16.h>

#define Tn 24
#define Bn 64
#define Dn 1536
#define Rn 5120
#define Cn 100
#define KSPLIT 8
#define KCH (Rn / KSPLIT)   // 640

__device__ __align__(16) __nv_bfloat16 g_W3[3u * Rn * Rn]; // 3-way exact split of WlT, [s][k][n]
__device__ __align__(16) __nv_bfloat16 g_spkbf[Bn * Rn];   // spike matrix [b][r], bf16 {0,1}
__device__ float g_xn[Tn * Bn * Dn];
__device__ float g_drive[Tn * Bn * Rn];
__device__ float g_mem[Bn * Rn];
__device__ float g_ttr[Bn * Rn];
__device__ float g_rtr[Bn * Rn];
__device__ float g_ctr[Bn * Rn];
__device__ float g_ssum[Bn * Rn];
__device__ float g_mempre[Bn * Rn];
__device__ float g_partial[KSPLIT][Bn * Rn];

// ---------------- init ----------------
__global__ void k_init()
{
    int i = blockIdx.x * 256 + threadIdx.x;
    if (i < Bn * Rn) {
        g_mem[i] = 0.f; g_ttr[i] = 0.f; g_rtr[i] = 0.f; g_ctr[i] = 0.f; g_ssum[i] = 0.f;
        g_spkbf[i] = __float2bfloat16_rn(0.f);
    }
}

// ---------------- masked transpose + exact 3-way bf16 split of Wl ----------------
__global__ void k_prepW3(const float* __restrict__ Wl, const float* __restrict__ lm)
{
    __shared__ float tile[32][33];
    int bx = blockIdx.x * 32;  // k (col of Wl)
    int by = blockIdx.y * 32;  // n (row of Wl)
    int x = bx + threadIdx.x;
#pragma unroll
    for (int j = 0; j < 32; j += 8) {
        int y = by + threadIdx.y + j;
        tile[threadIdx.y + j][threadIdx.x] = Wl[y * Rn + x] * lm[y * Rn + x];
    }
    __syncthreads();
    int xo = by + threadIdx.x;  // n
#pragma unroll
    for (int j = 0; j < 32; j += 8) {
        int yo = bx + threadIdx.y + j;  // k
        float w = tile[threadIdx.x][threadIdx.y + j];
        __nv_bfloat16 b1 = __float2bfloat16_rn(w);
        float f1 = __bfloat162float(b1);
        __nv_bfloat16 b2 = __float2bfloat16_rn(w - f1);
        float f2 = __bfloat162float(b2);
        __nv_bfloat16 b3 = __float2bfloat16_rn((w - f1) - f2);
        size_t o = (size_t)yo * Rn + xo;
        g_W3[o] = b1;
        g_W3[(size_t)Rn * Rn + o] = b2;
        g_W3[2u * (size_t)Rn * Rn + o] = b3;
    }
}

// ---------------- layernorm ----------------
__global__ void __launch_bounds__(256) k_ln(const float* __restrict__ x,
                                            const float* __restrict__ gw,
                                            const float* __restrict__ gb)
{
    const int row = blockIdx.x;
    const float* xr = x + row * Dn;
    float s = 0.f, s2 = 0.f;
    for (int i = threadIdx.x; i < Dn; i += 256) { float v = xr[i]; s += v; s2 += v * v; }
    __shared__ float sh[64];
    int lane = threadIdx.x & 31, wid = threadIdx.x >> 5;
#pragma unroll
    for (int o = 16; o > 0; o >>= 1) {
        s += __shfl_down_sync(0xffffffffu, s, o);
        s2 += __shfl_down_sync(0xffffffffu, s2, o);
    }
    if (lane == 0) { sh[wid] = s; sh[wid + 32] = s2; }
    __syncthreads();
    if (threadIdx.x == 0) {
        float ts = 0.f, ts2 = 0.f;
        for (int w = 0; w < 8; w++) { ts += sh[w]; ts2 += sh[w + 32]; }
        float mean = ts * (1.0f / Dn);
        float var = ts2 * (1.0f / Dn) - mean * mean;
        sh[0] = mean;
        sh[1] = rsqrtf(var + 1e-5f);
    }
    __syncthreads();
    float mean = sh[0], inv = sh[1];
    for (int i = threadIdx.x; i < Dn; i += 256)
        g_xn[row * Dn + i] = (xr[i] - mean) * inv * gw[i] + gb[i];
}

// ---------------- block-structured drive GEMM ----------------
__global__ void __launch_bounds__(256) k_drive(const float* __restrict__ Wp,
                                               const float* __restrict__ bp)
{
    __shared__ float As[16][128];
    __shared__ float Bs[16][128];
    const int bn = blockIdx.x, bm = blockIdx.y;
    const int nb = (bn * 128) >> 10;  // neuron block 0..4
    const int koff_t[5] = {0, 512, 1024, 1280, 1408};
    const int klen_t[5] = {512, 512, 256, 128, 0};
    const int k0 = koff_t[nb], kl = klen_t[nb];
    const int tid = threadIdx.x;
    const int tx = tid & 15, ty = tid >> 4;
    float acc[8][8];
#pragma unroll
    for (int i = 0; i < 8; i++)
#pragma unroll
        for (int j = 0; j < 8; j++) acc[i][j] = 0.f;

    const int ldm = tid >> 2;
    const int ldk = (tid & 3) << 2;
    for (int kt = 0; kt < kl; kt += 16) {
#pragma unroll
        for (int h = 0; h < 2; h++) {
            int m = ldm + h * 64;
            float4 av = *(const float4*)&g_xn[(bm * 128 + m) * Dn + k0 + kt + ldk];
            As[ldk + 0][m] = av.x; As[ldk + 1][m] = av.y; As[ldk + 2][m] = av.z; As[ldk + 3][m] = av.w;
            float4 bv = *(const float4*)&Wp[(bn * 128 + m) * Dn + k0 + kt + ldk];
            Bs[ldk + 0][m] = bv.x; Bs[ldk + 1][m] = bv.y; Bs[ldk + 2][m] = bv.z; Bs[ldk + 3][m] = bv.w;
        }
        __syncthreads();
#pragma unroll
        for (int k = 0; k < 16; k++) {
            float a[8], b[8];
#pragma unroll
            for (int i = 0; i < 8; i++) a[i] = As[k][ty * 8 + i];
#pragma unroll
            for (int j = 0; j < 8; j++) b[j] = Bs[k][tx * 8 + j];
#pragma unroll
            for (int i = 0; i < 8; i++)
#pragma unroll
                for (int j = 0; j < 8; j++) acc[i][j] += a[i] * b[j];
        }
        __syncthreads();
    }
#pragma unroll
    for (int i = 0; i < 8; i++) {
        int row = bm * 128 + ty * 8 + i;
#pragma unroll
        for (int j = 0; j < 8; j++) {
            int col = bn * 128 + tx * 8 + j;
            g_drive[row * Rn + col] = acc[i][j] + bp[col];
        }
    }
}

// ---------------- mma.sync helpers ----------------
__device__ __forceinline__ void ldmA(unsigned& r0, unsigned& r1, unsigned& r2, unsigned& r3, const void* p)
{
    unsigned a = (unsigned)__cvta_generic_to_shared(p);
    asm volatile("ldmatrix.sync.aligned.m8n8.x4.shared.b16 {%0,%1,%2,%3}, [%4];"
                 : "=r"(r0), "=r"(r1), "=r"(r2), "=r"(r3) : "r"(a));
}
__device__ __forceinline__ void ldmBT(unsigned& r0, unsigned& r1, unsigned& r2, unsigned& r3, const void* p)
{
    unsigned a = (unsigned)__cvta_generic_to_shared(p);
    asm volatile("ldmatrix.sync.aligned.m8n8.x4.trans.shared.b16 {%0,%1,%2,%3}, [%4];"
                 : "=r"(r0), "=r"(r1), "=r"(r2), "=r"(r3) : "r"(a));
}
__device__ __forceinline__ void mma16816(float c[4], const unsigned a[4], unsigned b0, unsigned b1)
{
    asm volatile("mma.sync.aligned.m16n8k16.row.col.f32.bf16.bf16.f32 "
                 "{%0,%1,%2,%3}, {%4,%5,%6,%7}, {%8,%9}, {%0,%1,%2,%3};"
                 : "+f"(c[0]), "+f"(c[1]), "+f"(c[2]), "+f"(c[3])
                 : "r"(a[0]), "r"(a[1]), "r"(a[2]), "r"(a[3]), "r"(b0), "r"(b1));
}

// ---------------- lateral recurrence: bf16 tensor-core GEMM, exact 3-split ----------------
// C[64 x 5120] = S[64 x 5120] @ (W1+W2+W3); grid (Rn/128, KSPLIT)
__global__ void __launch_bounds__(256) k_recg()
{
    __shared__ __nv_bfloat16 A_s[64][72];
    __shared__ __nv_bfloat16 B_s[64][136];
    const int tid = threadIdx.x;
    const int warp = tid >> 5, lane = tid & 31;
    const int wm = warp >> 1, wn = warp & 1;
    const int nt0 = blockIdx.x * 128;
    const int ks0 = blockIdx.y * KCH;

    float c[8][4];
#pragma unroll
    for (int i = 0; i < 8; i++)
#pragma unroll
        for (int j = 0; j < 4; j++) c[i][j] = 0.f;

    for (int s = 0; s < 3; s++) {
        const __nv_bfloat16* __restrict__ Wb = g_W3 + (size_t)s * Rn * Rn;
        for (int st = 0; st < KCH / 64; st++) {
            const int kb = ks0 + st * 64;
#pragma unroll
            for (int i = 0; i < 2; i++) {
                int idx = tid + i * 256;
                int row = idx >> 3, c8 = (idx & 7) * 8;
                *(uint4*)&A_s[row][c8] = *(const uint4*)&g_spkbf[row * Rn + kb + c8];
            }
#pragma unroll
            for (int i = 0; i < 4; i++) {
                int idx = tid + i * 256;
                int row = idx >> 4, c16 = (idx & 15) * 8;
                *(uint4*)&B_s[row][c16] = *(const uint4*)&Wb[(size_t)(kb + row) * Rn + nt0 + c16];
            }
            __syncthreads();
#pragma unroll
            for (int k16 = 0; k16 < 4; k16++) {
                unsigned a[4];
                ldmA(a[0], a[1], a[2], a[3], &A_s[wm * 16 + (lane & 15)][k16 * 16 + (lane >> 4) * 8]);
#pragma unroll
                for (int j = 0; j < 4; j++) {
                    unsigned b0, b1, b2, b3;
                    ldmBT(b0, b1, b2, b3, &B_s[k16 * 16 + (lane & 15)][wn * 64 + j * 16 + (lane >> 4) * 8]);
                    mma16816(c[2 * j + 0], a, b0, b1);
                    mma16816(c[2 * j + 1], a, b2, b3);
                }
            }
            __syncthreads();
        }
    }
    float* out = g_partial[blockIdx.y];
    const int g = lane >> 2, tc = (lane & 3) * 2;
#pragma unroll
    for (int j2 = 0; j2 < 8; j2++) {
        int colb = nt0 + wn * 64 + j2 * 8 + tc;
        int row0 = wm * 16 + g;
        *(float2*)&out[row0 * Rn + colb] = make_float2(c[j2][0], c[j2][1]);
        *(float2*)&out[(row0 + 8) * Rn + colb] = make_float2(c[j2][2], c[j2][3]);
    }
}

// ---------------- elementwise pre-WTA membrane (float4) ----------------
__global__ void __launch_bounds__(256) k_s1(int t,
                                            const float* __restrict__ bl,
                                            const float* __restrict__ decp,
                                            const float* __restrict__ refb,
                                            const float* __restrict__ curb)
{
    int idx = (blockIdx.x * 256 + threadIdx.x) * 4;
    int r = idx % Rn;
    float4 p = make_float4(0.f, 0.f, 0.f, 0.f);
#pragma unroll
    for (int s = 0; s < KSPLIT; s++) {
        float4 q = *(const float4*)&g_partial[s][idx];
        p.x += q.x; p.y += q.y; p.z += q.z; p.w += q.w;
    }
    float4 mem = *(const float4*)&g_mem[idx];
    float4 rtr = *(const float4*)&g_rtr[idx];
    float4 ctr = *(const float4*)&g_ctr[idx];
    float4 dr  = *(const float4*)&g_drive[t * (Bn * Rn) + idx];
    float4 dec = *(const float4*)&decp[r];
    float4 rb  = *(const float4*)&refb[r];
    float4 cb  = *(const float4*)&curb[r];
    float4 blv = *(const float4*)&bl[r];
    float4 o;
    {
        float spk = __bfloat162float(g_spkbf[idx + 0]);
        float d = fminf(fmaxf(dec.x, 0.f), 1.f);
        o.x = (mem.x - spk * (0.5f + rb.x * rtr.x)) * d + (dr.x + p.x + blv.x) + cb.x * ctr.x;
    }
    {
        float spk = __bfloat162float(g_spkbf[idx + 1]);
        float d = fminf(fmaxf(dec.y, 0.f), 1.f);
        o.y = (mem.y - spk * (0.5f + rb.y * rtr.y)) * d + (dr.y + p.y + blv.y) + cb.y * ctr.y;
    }
    {
        float spk = __bfloat162float(g_spkbf[idx + 2]);
        float d = fminf(fmaxf(dec.z, 0.f), 1.f);
        o.z = (mem.z - spk * (0.5f + rb.z * rtr.z)) * d + (dr.z + p.z + blv.z) + cb.z * ctr.z;
    }
    {
        float spk = __bfloat162float(g_spkbf[idx + 3]);
        float d = fminf(fmaxf(dec.w, 0.f), 1.f);
        o.w = (mem.w - spk * (0.5f + rb.w * rtr.w)) * d + (dr.w + p.w + blv.w) + cb.w * ctr.w;
    }
    *(float4*)&g_mempre[idx] = o;
}

// ---------------- WTA quantile + spike + traces ----------------
__device__ __forceinline__ unsigned f2key(float f)
{
    unsigned b = __float_as_uint(f);
    return (b & 0x80000000u) ? ~b : (b | 0x80000000u);
}
__device__ __forceinline__ float key2f(unsigned u)
{
    unsigned b = (u & 0x80000000u) ? (u & 0x7fffffffu) : ~u;
    return __uint_as_float(b);
}

__global__ void __launch_bounds__(256) k_s2(const float* __restrict__ thb,
                                            const float* __restrict__ thdp,
                                            const float* __restrict__ rfdp,
                                            const float* __restrict__ cudp)
{
    const int b = blockIdx.x, kq = blockIdx.y;
    const int tid = threadIdx.x;
    __shared__ int hist[256];
    __shared__ int wred[8];
    __shared__ int sh_rank;
    __shared__ unsigned sh_prefix;
    __shared__ int sh_cle;
    __shared__ unsigned sh_mg;

    float v[4]; unsigned u[4];
    const int base = b * Rn;
#pragma unroll
    for (int j = 0; j < 4; j++) {
        int r = (tid + j * 256) * 5 + kq;
        v[j] = g_mempre[base + r];
        u[j] = f2key(v[j]);
    }
    if (tid == 0) { sh_prefix = 0u; sh_rank = 818; sh_cle = 0; sh_mg = 0xffffffffu; }
    __syncthreads();
#pragma unroll
    for (int pass = 3; pass >= 0; pass--) {
        unsigned prefix = sh_prefix;
        int rank = sh_rank;
        hist[tid] = 0;
        __syncthreads();
        const int shv = pass * 8;
        const unsigned himask = (pass == 3) ? 0u : (0xffffffffu << ((shv + 8) & 31));
#pragma unroll
        for (int j = 0; j < 4; j++)
            if ((u[j] & himask) == prefix) atomicAdd(&hist[(u[j] >> shv) & 255], 1);
        __syncthreads();
        int c = hist[tid];
        int lane = tid & 31, wid = tid >> 5;
        int x = c;
#pragma unroll
        for (int o = 1; o < 32; o <<= 1) {
            int y = __shfl_up_sync(0xffffffffu, x, o);
            if (lane >= o) x += y;
        }
        if (lane == 31) wred[wid] = x;
        __syncthreads();
        int wofs = 0;
#pragma unroll
        for (int w = 0; w < 8; w++) if (w < wid) wofs += wred[w];
        int incl = x + wofs;
        int excl = incl - c;
        if (rank >= excl && rank < incl) {
            sh_prefix = prefix | ((unsigned)tid << shv);
            sh_rank = rank - excl;
        }
        __syncthreads();
    }
    unsigned u818 = sh_prefix;
    int cl = 0; unsigned mg = 0xffffffffu;
#pragma unroll
    for (int j = 0; j < 4; j++) {
        cl += (u[j] <= u818) ? 1 : 0;
        if (u[j] > u818) mg = min(mg, u[j]);
    }
    {
        int lane = tid & 31;
#pragma unroll
        for (int o = 16; o > 0; o >>= 1) {
            cl += __shfl_down_sync(0xffffffffu, cl, o);
            unsigned og = __shfl_down_sync(0xffffffffu, mg, o);
            mg = min(mg, og);
        }
        if (lane == 0) { atomicAdd(&sh_cle, cl); atomicMin(&sh_mg, mg); }
        __syncthreads();
    }
    unsigned u819 = (sh_cle >= 820) ? u818 : sh_mg;
    float v818 = key2f(u818), v819 = key2f(u819);
    // match jnp.quantile 'linear': idx = q*(n-1) in f32; out = lo*lw + hi*hw
    float qi = __fmul_rn(0.8f, 1023.0f);
    float hw = __fsub_rn(qi, 818.0f);
    float lw = __fsub_rn(1.0f, hw);
    float nps = __fadd_rn(__fmul_rn(v818, lw), __fmul_rn(v819, hw));

#pragma unroll
    for (int j = 0; j < 4; j++) {
        int r = (tid + j * 256) * 5 + kq;
        int idx = base + r;
        float m = v[j] - nps;
        m = m > 0.f ? m : 0.f;
        g_mem[idx] = m;
        float ttr = g_ttr[idx];
        float thr = 0.5f + thb[r] * ttr;
        float spk = (m - thr) > 0.f ? 1.f : 0.f;
        float thd = fminf(fmaxf(thdp[r], 0.f), 1.f);
        float rfd = fminf(fmaxf(rfdp[r], 0.f), 1.f);
        float cud = fminf(fmaxf(cudp[r], 0.f), 1.f);
        g_ttr[idx] = ttr * thd + spk;
        g_rtr[idx] = g_rtr[idx] * rfd + spk;
        g_ctr[idx] = g_ctr[idx] * cud + spk;
        g_ssum[idx] += spk;
        g_spkbf[idx] = __float2bfloat16_rn(spk);
    }
}

// ---------------- readout ----------------
__global__ void __launch_bounds__(256) k_out(const float* __restrict__ Wm,
                                             const float* __restrict__ bm,
                                             float* __restrict__ out)
{
    int b = blockIdx.x;
    __shared__ float row[Rn];
    for (int i = threadIdx.x; i < Rn; i += 256) row[i] = g_ssum[b * Rn + i] * (1.0f / 24.0f);
    __syncthreads();
    int wid = threadIdx.x >> 5, lane = threadIdx.x & 31;
    for (int c = wid; c < Cn; c += 8) {
        float s = 0.f;
        for (int i = lane; i < Rn; i += 32) s += row[i] * Wm[c * Rn + i];
#pragma unroll
        for (int o = 16; o > 0; o >>= 1) s += __shfl_down_sync(0xffffffffu, s, o);
        if (lane == 0) out[b * Cn + c] = s + bm[c];
    }
}

extern "C" void kernel_launch(void* const* d_in, const int* in_sizes, int n_in,
                              void* d_out, int out_size)
{
    const float* x      = (const float*)d_in[0];
    const float* ln_g   = (const float*)d_in[1];
    const float* ln_b   = (const float*)d_in[2];
    const float* Wp     = (const float*)d_in[3];
    const float* bp     = (const float*)d_in[4];
    const float* Wl     = (const float*)d_in[5];
    const float* bl     = (const float*)d_in[6];
    const float* Wm     = (const float*)d_in[7];
    const float* bm     = (const float*)d_in[8];
    const float* decay  = (const float*)d_in[9];
    const float* thrb   = (const float*)d_in[10];
    const float* thrd   = (const float*)d_in[11];
    const float* refb   = (const float*)d_in[12];
    const float* refd   = (const float*)d_in[13];
    const float* curb   = (const float*)d_in[14];
    const float* curd   = (const float*)d_in[15];
    const float* latm   = (const float*)d_in[17];
    float* out = (float*)d_out;

    k_init<<<1280, 256>>>();
    k_prepW3<<<dim3(160, 160), dim3(32, 8)>>>(Wl, latm);
    k_ln<<<Tn * Bn, 256>>>(x, ln_g, ln_b);
    k_drive<<<dim3(40, 12), 256>>>(Wp, bp);
    for (int t = 0; t < Tn; t++) {
        k_recg<<<dim3(Rn / 128, KSPLIT), 256>>>();
        k_s1<<<320, 256>>>(t, bl, decay, refb, curb);
        k_s2<<<dim3(Bn, 5), 256>>>(thrb, thrd, refd, curd);
    }
    k_out<<<Bn, 256>>>(Wm, bm, out);
}

// round 9
// speedup vs baseline: 2.3112x; 1.2307x over previous
#include <cuda_runtime.h>
#include <cuda_bf16.h>

#define Tn 24
#define Bn 64
#define Dn 1536
#define Rn 5120
#define Cn 100
#define KSPLIT 8
#define KCH (Rn / KSPLIT)   // 640

__device__ __align__(16) __nv_bfloat16 g_W3[3u * Rn * Rn]; // 3-way exact split of WlT, [s][k][n]
__device__ __align__(16) __nv_bfloat16 g_spkbf[Bn * Rn];   // spike matrix [b][r], bf16 {0,1}
__device__ float g_xn[Tn * Bn * Dn];
__device__ float g_drive[Tn * Bn * Rn];
__device__ float g_mem[Bn * Rn];
__device__ float g_ttr[Bn * Rn];
__device__ float g_rtr[Bn * Rn];
__device__ float g_ctr[Bn * Rn];
__device__ float g_ssum[Bn * Rn];
__device__ float g_mempre[Bn * Rn];
__device__ float g_partial[KSPLIT][Bn * Rn];

// ---------------- helpers ----------------
__device__ __forceinline__ void cpa16(void* dst, const void* src)
{
    unsigned d = (unsigned)__cvta_generic_to_shared(dst);
    asm volatile("cp.async.cg.shared.global [%0], [%1], 16;" :: "r"(d), "l"(src));
}
__device__ __forceinline__ void cpa_commit() { asm volatile("cp.async.commit_group;"); }
template<int N> __device__ __forceinline__ void cpa_wait() { asm volatile("cp.async.wait_group %0;" :: "n"(N)); }

__device__ __forceinline__ void ldmA(unsigned& r0, unsigned& r1, unsigned& r2, unsigned& r3, const void* p)
{
    unsigned a = (unsigned)__cvta_generic_to_shared(p);
    asm volatile("ldmatrix.sync.aligned.m8n8.x4.shared.b16 {%0,%1,%2,%3}, [%4];"
                 : "=r"(r0), "=r"(r1), "=r"(r2), "=r"(r3) : "r"(a));
}
__device__ __forceinline__ void ldmBT(unsigned& r0, unsigned& r1, unsigned& r2, unsigned& r3, const void* p)
{
    unsigned a = (unsigned)__cvta_generic_to_shared(p);
    asm volatile("ldmatrix.sync.aligned.m8n8.x4.trans.shared.b16 {%0,%1,%2,%3}, [%4];"
                 : "=r"(r0), "=r"(r1), "=r"(r2), "=r"(r3) : "r"(a));
}
__device__ __forceinline__ void mma16816(float c[4], const unsigned a[4], unsigned b0, unsigned b1)
{
    asm volatile("mma.sync.aligned.m16n8k16.row.col.f32.bf16.bf16.f32 "
                 "{%0,%1,%2,%3}, {%4,%5,%6,%7}, {%8,%9}, {%0,%1,%2,%3};"
                 : "+f"(c[0]), "+f"(c[1]), "+f"(c[2]), "+f"(c[3])
                 : "r"(a[0]), "r"(a[1]), "r"(a[2]), "r"(a[3]), "r"(b0), "r"(b1));
}

// ---------------- init ----------------
__global__ void k_init()
{
    int i = blockIdx.x * 256 + threadIdx.x;
    if (i < Bn * Rn) {
        g_mem[i] = 0.f; g_ttr[i] = 0.f; g_rtr[i] = 0.f; g_ctr[i] = 0.f; g_ssum[i] = 0.f;
        g_spkbf[i] = __float2bfloat16_rn(0.f);
    }
}

// ---------------- masked transpose + exact 3-way bf16 split of Wl ----------------
__global__ void k_prepW3(const float* __restrict__ Wl, const float* __restrict__ lm)
{
    __shared__ float tile[32][33];
    int bx = blockIdx.x * 32;  // k (col of Wl)
    int by = blockIdx.y * 32;  // n (row of Wl)
    int x = bx + threadIdx.x;
#pragma unroll
    for (int j = 0; j < 32; j += 8) {
        int y = by + threadIdx.y + j;
        tile[threadIdx.y + j][threadIdx.x] = Wl[y * Rn + x] * lm[y * Rn + x];
    }
    __syncthreads();
    int xo = by + threadIdx.x;  // n
#pragma unroll
    for (int j = 0; j < 32; j += 8) {
        int yo = bx + threadIdx.y + j;  // k
        float w = tile[threadIdx.x][threadIdx.y + j];
        __nv_bfloat16 b1 = __float2bfloat16_rn(w);
        float f1 = __bfloat162float(b1);
        __nv_bfloat16 b2 = __float2bfloat16_rn(w - f1);
        float f2 = __bfloat162float(b2);
        __nv_bfloat16 b3 = __float2bfloat16_rn((w - f1) - f2);
        size_t o = (size_t)yo * Rn + xo;
        g_W3[o] = b1;
        g_W3[(size_t)Rn * Rn + o] = b2;
        g_W3[2u * (size_t)Rn * Rn + o] = b3;
    }
}

// ---------------- layernorm ----------------
__global__ void __launch_bounds__(256) k_ln(const float* __restrict__ x,
                                            const float* __restrict__ gw,
                                            const float* __restrict__ gb)
{
    const int row = blockIdx.x;
    const float* xr = x + row * Dn;
    float s = 0.f, s2 = 0.f;
    for (int i = threadIdx.x; i < Dn; i += 256) { float v = xr[i]; s += v; s2 += v * v; }
    __shared__ float sh[64];
    int lane = threadIdx.x & 31, wid = threadIdx.x >> 5;
#pragma unroll
    for (int o = 16; o > 0; o >>= 1) {
        s += __shfl_down_sync(0xffffffffu, s, o);
        s2 += __shfl_down_sync(0xffffffffu, s2, o);
    }
    if (lane == 0) { sh[wid] = s; sh[wid + 32] = s2; }
    __syncthreads();
    if (threadIdx.x == 0) {
        float ts = 0.f, ts2 = 0.f;
        for (int w = 0; w < 8; w++) { ts += sh[w]; ts2 += sh[w + 32]; }
        float mean = ts * (1.0f / Dn);
        float var = ts2 * (1.0f / Dn) - mean * mean;
        sh[0] = mean;
        sh[1] = rsqrtf(var + 1e-5f);
    }
    __syncthreads();
    float mean = sh[0], inv = sh[1];
    for (int i = threadIdx.x; i < Dn; i += 256)
        g_xn[row * Dn + i] = (xr[i] - mean) * inv * gw[i] + gb[i];
}

// ---------------- block-structured drive GEMM (fp32 SIMT — proven bit-stable) ----------------
__global__ void __launch_bounds__(256) k_drive(const float* __restrict__ Wp,
                                               const float* __restrict__ bp)
{
    __shared__ float As[16][128];
    __shared__ float Bs[16][128];
    const int bn = blockIdx.x, bm = blockIdx.y;
    const int nb = (bn * 128) >> 10;  // neuron block 0..4
    const int koff_t[5] = {0, 512, 1024, 1280, 1408};
    const int klen_t[5] = {512, 512, 256, 128, 0};
    const int k0 = koff_t[nb], kl = klen_t[nb];
    const int tid = threadIdx.x;
    const int tx = tid & 15, ty = tid >> 4;
    float acc[8][8];
#pragma unroll
    for (int i = 0; i < 8; i++)
#pragma unroll
        for (int j = 0; j < 8; j++) acc[i][j] = 0.f;

    const int ldm = tid >> 2;
    const int ldk = (tid & 3) << 2;
    for (int kt = 0; kt < kl; kt += 16) {
#pragma unroll
        for (int h = 0; h < 2; h++) {
            int m = ldm + h * 64;
            float4 av = *(const float4*)&g_xn[(bm * 128 + m) * Dn + k0 + kt + ldk];
            As[ldk + 0][m] = av.x; As[ldk + 1][m] = av.y; As[ldk + 2][m] = av.z; As[ldk + 3][m] = av.w;
            float4 bv = *(const float4*)&Wp[(bn * 128 + m) * Dn + k0 + kt + ldk];
            Bs[ldk + 0][m] = bv.x; Bs[ldk + 1][m] = bv.y; Bs[ldk + 2][m] = bv.z; Bs[ldk + 3][m] = bv.w;
        }
        __syncthreads();
#pragma unroll
        for (int k = 0; k < 16; k++) {
            float a[8], b[8];
#pragma unroll
            for (int i = 0; i < 8; i++) a[i] = As[k][ty * 8 + i];
#pragma unroll
            for (int j = 0; j < 8; j++) b[j] = Bs[k][tx * 8 + j];
#pragma unroll
            for (int i = 0; i < 8; i++)
#pragma unroll
                for (int j = 0; j < 8; j++) acc[i][j] += a[i] * b[j];
        }
        __syncthreads();
    }
#pragma unroll
    for (int i = 0; i < 8; i++) {
        int row = bm * 128 + ty * 8 + i;
#pragma unroll
        for (int j = 0; j < 8; j++) {
            int col = bn * 128 + tx * 8 + j;
            g_drive[row * Rn + col] = acc[i][j] + bp[col];
        }
    }
}

// ---------------- lateral recurrence: bf16 TC GEMM, exact 3-split, cp.async pipelined ----
// Identical accumulation order to the R6 (passing) kernel: s outer, 10 k-chunks of 64.
__global__ void __launch_bounds__(256) k_recg()
{
    extern __shared__ char sm[];
    __nv_bfloat16* Abuf = (__nv_bfloat16*)sm;            // [2][64][72]
    __nv_bfloat16* Bbuf = (__nv_bfloat16*)(sm + 18432);  // [2][64][136]
    const int tid = threadIdx.x;
    const int warp = tid >> 5, lane = tid & 31;
    const int wm = warp >> 1, wn = warp & 1;
    const int nt0 = blockIdx.x * 128;
    const int ks0 = blockIdx.y * KCH;
    const int SPK = KCH / 64;        // 10
    const int NST = 3 * SPK;         // 30

    float c[8][4];
#pragma unroll
    for (int i = 0; i < 8; i++)
#pragma unroll
        for (int j = 0; j < 4; j++) c[i][j] = 0.f;

    auto load_stage = [&](int st, int buf) {
        int s = st / SPK, stq = st - s * SPK;
        const __nv_bfloat16* Wb = g_W3 + (size_t)s * Rn * Rn;
        int kb = ks0 + stq * 64;
#pragma unroll
        for (int i = 0; i < 2; i++) {   // 512 x 16B: full 64x64 bf16 A tile
            int idx = tid + i * 256;
            int row = idx >> 3, ch = (idx & 7) * 8;
            cpa16(&Abuf[buf * 4608 + row * 72 + ch], &g_spkbf[row * Rn + kb + ch]);
        }
#pragma unroll
        for (int i = 0; i < 4; i++) {   // 1024 x 16B: full 64x128 bf16 B tile
            int idx = tid + i * 256;
            int row = idx >> 4, ch = (idx & 15) * 8;
            cpa16(&Bbuf[buf * 8704 + row * 136 + ch], &Wb[(size_t)(kb + row) * Rn + nt0 + ch]);
        }
        cpa_commit();
    };

    load_stage(0, 0);
    for (int st = 0; st < NST; st++) {
        int buf = st & 1;
        if (st + 1 < NST) { load_stage(st + 1, (st + 1) & 1); cpa_wait<1>(); }
        else cpa_wait<0>();
        __syncthreads();
#pragma unroll
        for (int k16 = 0; k16 < 4; k16++) {
            unsigned a[4];
            ldmA(a[0], a[1], a[2], a[3],
                 &Abuf[buf * 4608 + (wm * 16 + (lane & 15)) * 72 + k16 * 16 + (lane >> 4) * 8]);
#pragma unroll
            for (int j = 0; j < 4; j++) {
                unsigned b0, b1, b2, b3;
                ldmBT(b0, b1, b2, b3,
                      &Bbuf[buf * 8704 + (k16 * 16 + (lane & 15)) * 136 + wn * 64 + j * 16 + (lane >> 4) * 8]);
                mma16816(c[2 * j + 0], a, b0, b1);
                mma16816(c[2 * j + 1], a, b2, b3);
            }
        }
        __syncthreads();
    }
    float* out = g_partial[blockIdx.y];
    const int g = lane >> 2, tc = (lane & 3) * 2;
#pragma unroll
    for (int j2 = 0; j2 < 8; j2++) {
        int colb = nt0 + wn * 64 + j2 * 8 + tc;
        int row0 = wm * 16 + g;
        *(float2*)&out[row0 * Rn + colb] = make_float2(c[j2][0], c[j2][1]);
        *(float2*)&out[(row0 + 8) * Rn + colb] = make_float2(c[j2][2], c[j2][3]);
    }
}

// ---------------- elementwise pre-WTA membrane (float4) ----------------
__global__ void __launch_bounds__(256) k_s1(int t,
                                            const float* __restrict__ bl,
                                            const float* __restrict__ decp,
                                            const float* __restrict__ refb,
                                            const float* __restrict__ curb)
{
    int idx = (blockIdx.x * 256 + threadIdx.x) * 4;
    int r = idx % Rn;
    float4 p = make_float4(0.f, 0.f, 0.f, 0.f);
#pragma unroll
    for (int s = 0; s < KSPLIT; s++) {
        float4 q = *(const float4*)&g_partial[s][idx];
        p.x += q.x; p.y += q.y; p.z += q.z; p.w += q.w;
    }
    float4 mem = *(const float4*)&g_mem[idx];
    float4 rtr = *(const float4*)&g_rtr[idx];
    float4 ctr = *(const float4*)&g_ctr[idx];
    float4 dr  = *(const float4*)&g_drive[(size_t)t * (Bn * Rn) + idx];
    float4 dec = *(const float4*)&decp[r];
    float4 rb  = *(const float4*)&refb[r];
    float4 cb  = *(const float4*)&curb[r];
    float4 blv = *(const float4*)&bl[r];
    float4 o;
    {
        float spk = __bfloat162float(g_spkbf[idx + 0]);
        float d = fminf(fmaxf(dec.x, 0.f), 1.f);
        o.x = (mem.x - spk * (0.5f + rb.x * rtr.x)) * d + (dr.x + p.x + blv.x) + cb.x * ctr.x;
    }
    {
        float spk = __bfloat162float(g_spkbf[idx + 1]);
        float d = fminf(fmaxf(dec.y, 0.f), 1.f);
        o.y = (mem.y - spk * (0.5f + rb.y * rtr.y)) * d + (dr.y + p.y + blv.y) + cb.y * ctr.y;
    }
    {
        float spk = __bfloat162float(g_spkbf[idx + 2]);
        float d = fminf(fmaxf(dec.z, 0.f), 1.f);
        o.z = (mem.z - spk * (0.5f + rb.z * rtr.z)) * d + (dr.z + p.z + blv.z) + cb.z * ctr.z;
    }
    {
        float spk = __bfloat162float(g_spkbf[idx + 3]);
        float d = fminf(fmaxf(dec.w, 0.f), 1.f);
        o.w = (mem.w - spk * (0.5f + rb.w * rtr.w)) * d + (dr.w + p.w + blv.w) + cb.w * ctr.w;
    }
    *(float4*)&g_mempre[idx] = o;
}

// ---------------- WTA quantile + spike + traces ----------------
__device__ __forceinline__ unsigned f2key(float f)
{
    unsigned b = __float_as_uint(f);
    return (b & 0x80000000u) ? ~b : (b | 0x80000000u);
}
__device__ __forceinline__ float key2f(unsigned u)
{
    unsigned b = (u & 0x80000000u) ? (u & 0x7fffffffu) : ~u;
    return __uint_as_float(b);
}

__global__ void __launch_bounds__(256) k_s2(const float* __restrict__ thb,
                                            const float* __restrict__ thdp,
                                            const float* __restrict__ rfdp,
                                            const float* __restrict__ cudp)
{
    const int b = blockIdx.x, kq = blockIdx.y;
    const int tid = threadIdx.x;
    __shared__ int hist[256];
    __shared__ int wred[8];
    __shared__ int sh_rank;
    __shared__ unsigned sh_prefix;
    __shared__ int sh_cle;
    __shared__ unsigned sh_mg;

    float v[4]; unsigned u[4];
    const int base = b * Rn;
#pragma unroll
    for (int j = 0; j < 4; j++) {
        int r = (tid + j * 256) * 5 + kq;
        v[j] = g_mempre[base + r];
        u[j] = f2key(v[j]);
    }
    if (tid == 0) { sh_prefix = 0u; sh_rank = 818; sh_cle = 0; sh_mg = 0xffffffffu; }
    __syncthreads();
#pragma unroll
    for (int pass = 3; pass >= 0; pass--) {
        unsigned prefix = sh_prefix;
        int rank = sh_rank;
        hist[tid] = 0;
        __syncthreads();
        const int shv = pass * 8;
        const unsigned himask = (pass == 3) ? 0u : (0xffffffffu << ((shv + 8) & 31));
#pragma unroll
        for (int j = 0; j < 4; j++)
            if ((u[j] & himask) == prefix) atomicAdd(&hist[(u[j] >> shv) & 255], 1);
        __syncthreads();
        int c = hist[tid];
        int lane = tid & 31, wid = tid >> 5;
        int x = c;
#pragma unroll
        for (int o = 1; o < 32; o <<= 1) {
            int y = __shfl_up_sync(0xffffffffu, x, o);
            if (lane >= o) x += y;
        }
        if (lane == 31) wred[wid] = x;
        __syncthreads();
        int wofs = 0;
#pragma unroll
        for (int w = 0; w < 8; w++) if (w < wid) wofs += wred[w];
        int incl = x + wofs;
        int excl = incl - c;
        if (rank >= excl && rank < incl) {
            sh_prefix = prefix | ((unsigned)tid << shv);
            sh_rank = rank - excl;
        }
        __syncthreads();
    }
    unsigned u818 = sh_prefix;
    int cl = 0; unsigned mg = 0xffffffffu;
#pragma unroll
    for (int j = 0; j < 4; j++) {
        cl += (u[j] <= u818) ? 1 : 0;
        if (u[j] > u818) mg = min(mg, u[j]);
    }
    {
        int lane = tid & 31;
#pragma unroll
        for (int o = 16; o > 0; o >>= 1) {
            cl += __shfl_down_sync(0xffffffffu, cl, o);
            unsigned og = __shfl_down_sync(0xffffffffu, mg, o);
            mg = min(mg, og);
        }
        if (lane == 0) { atomicAdd(&sh_cle, cl); atomicMin(&sh_mg, mg); }
        __syncthreads();
    }
    unsigned u819 = (sh_cle >= 820) ? u818 : sh_mg;
    float v818 = key2f(u818), v819 = key2f(u819);
    float qi = __fmul_rn(0.8f, 1023.0f);
    float hw = __fsub_rn(qi, 818.0f);
    float lw = __fsub_rn(1.0f, hw);
    float nps = __fadd_rn(__fmul_rn(v818, lw), __fmul_rn(v819, hw));

#pragma unroll
    for (int j = 0; j < 4; j++) {
        int r = (tid + j * 256) * 5 + kq;
        int idx = base + r;
        float m = v[j] - nps;
        m = m > 0.f ? m : 0.f;
        g_mem[idx] = m;
        float ttr = g_ttr[idx];
        float thr = 0.5f + thb[r] * ttr;
        float spk = (m - thr) > 0.f ? 1.f : 0.f;
        float thd = fminf(fmaxf(thdp[r], 0.f), 1.f);
        float rfd = fminf(fmaxf(rfdp[r], 0.f), 1.f);
        float cud = fminf(fmaxf(cudp[r], 0.f), 1.f);
        g_ttr[idx] = ttr * thd + spk;
        g_rtr[idx] = g_rtr[idx] * rfd + spk;
        g_ctr[idx] = g_ctr[idx] * cud + spk;
        g_ssum[idx] += spk;
        g_spkbf[idx] = __float2bfloat16_rn(spk);
    }
}

// ---------------- readout ----------------
__global__ void __launch_bounds__(256) k_out(const float* __restrict__ Wm,
                                             const float* __restrict__ bm,
                                             float* __restrict__ out)
{
    int b = blockIdx.x;
    __shared__ float row[Rn];
    for (int i = threadIdx.x; i < Rn; i += 256) row[i] = g_ssum[b * Rn + i] * (1.0f / 24.0f);
    __syncthreads();
    int wid = threadIdx.x >> 5, lane = threadIdx.x & 31;
    for (int c = wid; c < Cn; c += 8) {
        float s = 0.f;
        for (int i = lane; i < Rn; i += 32) s += row[i] * Wm[c * Rn + i];
#pragma unroll
        for (int o = 16; o > 0; o >>= 1) s += __shfl_down_sync(0xffffffffu, s, o);
        if (lane == 0) out[b * Cn + c] = s + bm[c];
    }
}

extern "C" void kernel_launch(void* const* d_in, const int* in_sizes, int n_in,
                              void* d_out, int out_size)
{
    const float* x      = (const float*)d_in[0];
    const float* ln_g   = (const float*)d_in[1];
    const float* ln_b   = (const float*)d_in[2];
    const float* Wp     = (const float*)d_in[3];
    const float* bp     = (const float*)d_in[4];
    const float* Wl     = (const float*)d_in[5];
    const float* bl     = (const float*)d_in[6];
    const float* Wm     = (const float*)d_in[7];
    const float* bm     = (const float*)d_in[8];
    const float* decay  = (const float*)d_in[9];
    const float* thrb   = (const float*)d_in[10];
    const float* thrd   = (const float*)d_in[11];
    const float* refb   = (const float*)d_in[12];
    const float* refd   = (const float*)d_in[13];
    const float* curb   = (const float*)d_in[14];
    const float* curd   = (const float*)d_in[15];
    const float* latm   = (const float*)d_in[17];
    float* out = (float*)d_out;

    const int smemRec = 2 * (64 * 72 + 64 * 136) * 2;        // 53248
    cudaFuncSetAttribute(k_recg, cudaFuncAttributeMaxDynamicSharedMemorySize, smemRec);

    k_init<<<1280, 256>>>();
    k_prepW3<<<dim3(160, 160), dim3(32, 8)>>>(Wl, latm);
    k_ln<<<Tn * Bn, 256>>>(x, ln_g, ln_b);
    k_drive<<<dim3(40, 12), 256>>>(Wp, bp);
    for (int t = 0; t < Tn; t++) {
        k_recg<<<dim3(Rn / 128, KSPLIT), 256, smemRec>>>();
        k_s1<<<320, 256>>>(t, bl, decay, refb, curb);
        k_s2<<<dim3(Bn, 5), 256>>>(thrb, thrd, refd, curd);
    }
    k_out<<<Bn, 256>>>(Wm, bm, out);
}